// round 1
// baseline (speedup 1.0000x reference)
#include <cuda_runtime.h>
#include <math.h>

#define Bsz   4096
#define Dd    256
#define Ccls  10
#define Nrows 8192
#define TILES 64          // 8192 / 128
#define NBLK  2080        // 64*65/2 triangular tiles

// ---------------- device scratch (no allocations allowed) ----------------
__device__ float g_sq[Nrows];
__device__ float g_vecsum[Dd];
__device__ float g_sumsq;
__device__ float g_ssum[Ccls];
__device__ float g_tsum[Ccls];
__device__ int   g_cnt[Ccls];
__device__ float g_sscale[Ccls];
__device__ float g_tscale[Ccls];   // carries the minus sign for target rows
__device__ float g_expC;           // 1/(16*bw') = 1/(4*bw_raw)
__device__ float g_invcount;

// ---------------- kernel 0: zero accumulators + output -------------------
__global__ void k_zero(float* out) {
    int t = threadIdx.x;
    if (t < Dd)   g_vecsum[t] = 0.f;
    if (t < Ccls) { g_ssum[t] = 0.f; g_tsum[t] = 0.f; g_cnt[t] = 0; }
    if (t == 0)   { g_sumsq = 0.f; out[0] = 0.f; }
}

// ---------------- kernel 1: label/logit column stats ----------------------
// grid 16 x 256, one thread per row of the 4096 x 10 matrices
__global__ void k_stats(const float* __restrict__ slab,
                        const float* __restrict__ tlog) {
    __shared__ float sp[Ccls], tp[Ccls];
    __shared__ int   cp[Ccls];
    int t = threadIdx.x;
    if (t < Ccls) { sp[t] = 0.f; tp[t] = 0.f; cp[t] = 0; }
    __syncthreads();
    int r = blockIdx.x * 256 + t;
    float best = -1.f; int bidx = 0;
    #pragma unroll
    for (int c = 0; c < Ccls; c++) {
        float sv = slab[(size_t)r * Ccls + c];
        float tv = tlog[(size_t)r * Ccls + c];
        atomicAdd(&sp[c], sv);
        atomicAdd(&tp[c], tv);
        if (tv > best) { best = tv; bidx = c; }   // first-max like jnp.argmax
    }
    atomicAdd(&cp[bidx], 1);
    __syncthreads();
    if (t < Ccls) {
        atomicAdd(&g_ssum[t], sp[t]);
        atomicAdd(&g_tsum[t], tp[t]);
        atomicAdd(&g_cnt[t],  cp[t]);
    }
}

// ---------------- kernel 2: per-row squared norms + total -----------------
// one warp per row; grid 1024 x 256
__global__ void k_sq(const float* __restrict__ src,
                     const float* __restrict__ tgt) {
    int w = threadIdx.x >> 5, lane = threadIdx.x & 31;
    int row = blockIdx.x * 8 + w;
    const float* p = (row < Bsz) ? src + (size_t)row * Dd
                                 : tgt + (size_t)(row - Bsz) * Dd;
    float s = 0.f;
    #pragma unroll
    for (int i = 0; i < 8; i++) { float v = p[lane + 32 * i]; s += v * v; }
    #pragma unroll
    for (int o = 16; o; o >>= 1) s += __shfl_xor_sync(0xffffffffu, s, o);
    __shared__ float bs[8];
    if (lane == 0) { g_sq[row] = s; bs[w] = s; }
    __syncthreads();
    if (threadIdx.x == 0) {
        float tsum = 0.f;
        #pragma unroll
        for (int i = 0; i < 8; i++) tsum += bs[i];
        atomicAdd(&g_sumsq, tsum);
    }
}

// ---------------- kernel 3: per-dimension sum vector ----------------------
// grid 64 x 256; block handles 128 consecutive rows (never straddles src/tgt)
__global__ void k_vecsum(const float* __restrict__ src,
                         const float* __restrict__ tgt) {
    int d = threadIdx.x;
    int r0 = blockIdx.x * 128;
    const float* base = (r0 < Bsz) ? src + (size_t)r0 * Dd
                                   : tgt + (size_t)(r0 - Bsz) * Dd;
    float s = 0.f;
    #pragma unroll 8
    for (int i = 0; i < 128; i++) s += base[(size_t)i * Dd + d];
    atomicAdd(&g_vecsum[d], s);
}

// ---------------- kernel 4: finalize scales / bandwidth -------------------
__global__ void k_final() {
    int t = threadIdx.x;
    __shared__ float red[256];
    if (t < Ccls) {
        float s = g_ssum[t];
        int   c = g_cnt[t];
        bool mask = (s > 0.f) && (c > 0);
        g_sscale[t] = mask ? (1.f / s) : 0.f;
        float te = g_tsum[t]; te = (te == 0.f) ? 100.f : te;
        g_tscale[t] = mask ? (-1.f / te) : 0.f;   // minus sign folds cross-term
    }
    float v = g_vecsum[t];
    red[t] = v * v;
    __syncthreads();
    for (int s = 128; s; s >>= 1) { if (t < s) red[t] += red[t + s]; __syncthreads(); }
    if (t == 0) {
        int count = 0;
        for (int c = 0; c < Ccls; c++)
            if (g_ssum[c] > 0.f && g_cnt[c] > 0) count++;
        float VV = red[0];
        float S  = g_sumsq;
        // sum of all pairwise L2 distances, analytically (diag contributes 0)
        float sum_l2 = 2.f * (float)Nrows * S - 2.f * VV;
        float nf = (float)Nrows;
        float bw_raw = sum_l2 / (nf * nf - nf);
        // bandwidth' = bw_raw / mul^(num//2) = bw_raw/4 ; z uses 16*bw'
        g_expC = 1.f / (4.f * bw_raw);
        g_invcount = (count > 0) ? 1.f / (float)count : 0.f;
    }
}

// ---------------- kernel 5: fused pairwise GEMM + MMD epilogue ------------
// 128x128 tile per block, 256 threads, 8x8 micro-tile, triangular grid.
__global__ void __launch_bounds__(256) k_main(
    const float* __restrict__ src, const float* __restrict__ tgt,
    const float* __restrict__ slab, const float* __restrict__ tlog,
    float* __restrict__ out)
{
    __shared__ float As[32][132];
    __shared__ float Bs[32][132];
    __shared__ float uP[Ccls][132];
    __shared__ float uQ[Ccls][132];
    __shared__ float sqP[128], sqQ[128];
    __shared__ float redsh[8];

    int b = blockIdx.x;
    // decode (bi <= bj) from linear triangular index
    int bi = (int)((2.f * TILES + 1.f -
                    sqrtf((float)((2 * TILES + 1) * (2 * TILES + 1) - 8 * b))) * 0.5f);
    if (bi < 0) bi = 0; if (bi > TILES - 1) bi = TILES - 1;
    while (bi > 0 && bi * TILES - bi * (bi - 1) / 2 > b) bi--;
    while ((bi + 1) * TILES - (bi + 1) * bi / 2 <= b) bi++;
    int bj = bi + (b - (bi * TILES - bi * (bi - 1) / 2));

    int p0 = bi * 128, q0 = bj * 128;
    const float* Ab = (p0 < Bsz) ? src + (size_t)p0 * Dd : tgt + (size_t)(p0 - Bsz) * Dd;
    const float* Bb = (q0 < Bsz) ? src + (size_t)q0 * Dd : tgt + (size_t)(q0 - Bsz) * Dd;

    int tid = threadIdx.x;

    // load weight vectors u (scaled, sign-carrying) and squared norms
    if (tid < 128) {
        int p = p0 + tid;
        sqP[tid] = g_sq[p];
        if (p < Bsz) {
            #pragma unroll
            for (int c = 0; c < Ccls; c++)
                uP[c][tid] = slab[(size_t)p * Ccls + c] * g_sscale[c];
        } else {
            #pragma unroll
            for (int c = 0; c < Ccls; c++)
                uP[c][tid] = tlog[(size_t)(p - Bsz) * Ccls + c] * g_tscale[c];
        }
    } else {
        int j = tid - 128;
        int q = q0 + j;
        sqQ[j] = g_sq[q];
        if (q < Bsz) {
            #pragma unroll
            for (int c = 0; c < Ccls; c++)
                uQ[c][j] = slab[(size_t)q * Ccls + c] * g_sscale[c];
        } else {
            #pragma unroll
            for (int c = 0; c < Ccls; c++)
                uQ[c][j] = tlog[(size_t)(q - Bsz) * Ccls + c] * g_tscale[c];
        }
    }

    const int tx = tid & 15, ty = tid >> 4;

    float acc[8][8];
    #pragma unroll
    for (int r = 0; r < 8; r++)
        #pragma unroll
        for (int c = 0; c < 8; c++) acc[r][c] = 0.f;

    // ---- mainloop: dot(x_p, x_q) over D=256 in 8 chunks of 32 ----
    for (int kt = 0; kt < Dd / 32; kt++) {
        __syncthreads();
        #pragma unroll
        for (int i = 0; i < 4; i++) {
            int g = tid + 256 * i;        // 0..1023
            int row = g >> 3;
            int kq  = g & 7;
            const float4 va = *(const float4*)(Ab + (size_t)row * Dd + kt * 32 + kq * 4);
            const float4 vb = *(const float4*)(Bb + (size_t)row * Dd + kt * 32 + kq * 4);
            As[kq * 4 + 0][row] = va.x; As[kq * 4 + 1][row] = va.y;
            As[kq * 4 + 2][row] = va.z; As[kq * 4 + 3][row] = va.w;
            Bs[kq * 4 + 0][row] = vb.x; Bs[kq * 4 + 1][row] = vb.y;
            Bs[kq * 4 + 2][row] = vb.z; Bs[kq * 4 + 3][row] = vb.w;
        }
        __syncthreads();
        #pragma unroll 4
        for (int kk = 0; kk < 32; kk++) {
            float4 a0 = *(const float4*)&As[kk][ty * 8];
            float4 a1 = *(const float4*)&As[kk][ty * 8 + 4];
            float4 b0 = *(const float4*)&Bs[kk][tx * 8];
            float4 b1 = *(const float4*)&Bs[kk][tx * 8 + 4];
            float a[8] = {a0.x, a0.y, a0.z, a0.w, a1.x, a1.y, a1.z, a1.w};
            float bb[8] = {b0.x, b0.y, b0.z, b0.w, b1.x, b1.y, b1.z, b1.w};
            #pragma unroll
            for (int r = 0; r < 8; r++)
                #pragma unroll
                for (int c = 0; c < 8; c++)
                    acc[r][c] = fmaf(a[r], bb[c], acc[r][c]);
        }
    }

    // ---- 10-deep weight GEMM: w = u_p . u_q (sign included) ----
    float wacc[8][8];
    #pragma unroll
    for (int r = 0; r < 8; r++)
        #pragma unroll
        for (int c = 0; c < 8; c++) wacc[r][c] = 0.f;
    #pragma unroll
    for (int cc = 0; cc < Ccls; cc++) {
        float4 a0 = *(const float4*)&uP[cc][ty * 8];
        float4 a1 = *(const float4*)&uP[cc][ty * 8 + 4];
        float4 b0 = *(const float4*)&uQ[cc][tx * 8];
        float4 b1 = *(const float4*)&uQ[cc][tx * 8 + 4];
        float a[8] = {a0.x, a0.y, a0.z, a0.w, a1.x, a1.y, a1.z, a1.w};
        float bb[8] = {b0.x, b0.y, b0.z, b0.w, b1.x, b1.y, b1.z, b1.w};
        #pragma unroll
        for (int r = 0; r < 8; r++)
            #pragma unroll
            for (int c = 0; c < 8; c++)
                wacc[r][c] = fmaf(a[r], bb[c], wacc[r][c]);
    }

    // ---- epilogue: l2 -> multi-bandwidth gaussian via one exp ----
    float sp[8], sv[8];
    #pragma unroll
    for (int r = 0; r < 8; r++) sp[r] = sqP[ty * 8 + r];
    #pragma unroll
    for (int c = 0; c < 8; c++) sv[c] = sqQ[tx * 8 + c];
    const float Ce = g_expC;
    const float scale = g_invcount * ((bi == bj) ? 1.f : 2.f);

    float partial = 0.f;
    #pragma unroll
    for (int r = 0; r < 8; r++)
        #pragma unroll
        for (int c = 0; c < 8; c++) {
            float l2 = fmaxf(sp[r] + sv[c] - 2.f * acc[r][c], 0.f);
            float z  = __expf(-l2 * Ce);        // z = exp(-l2/(16*bw'))
            float z2 = z * z, z4 = z2 * z2, z8 = z4 * z4;
            // sum over 5 bandwidths: z + z^2 + z^4 + z^8 + z^16
            partial += wacc[r][c] * (z + z2 + z4 + z8 + z8 * z8);
        }
    partial *= scale;

    #pragma unroll
    for (int o = 16; o; o >>= 1) partial += __shfl_xor_sync(0xffffffffu, partial, o);
    if ((tid & 31) == 0) redsh[tid >> 5] = partial;
    __syncthreads();
    if (tid == 0) {
        float s = 0.f;
        #pragma unroll
        for (int i = 0; i < 8; i++) s += redsh[i];
        atomicAdd(out, s);
    }
}

// ---------------- launcher ------------------------------------------------
extern "C" void kernel_launch(void* const* d_in, const int* in_sizes, int n_in,
                              void* d_out, int out_size) {
    const float* src  = (const float*)d_in[0];
    const float* tgt  = (const float*)d_in[1];
    const float* slab = (const float*)d_in[2];
    const float* tlog = (const float*)d_in[3];
    float* out = (float*)d_out;

    k_zero<<<1, 256>>>(out);
    k_stats<<<Bsz / 256, 256>>>(slab, tlog);
    k_sq<<<Nrows / 8, 256>>>(src, tgt);
    k_vecsum<<<Nrows / 128, 256>>>(src, tgt);
    k_final<<<1, 256>>>();
    k_main<<<NBLK, 256>>>(src, tgt, slab, tlog, out);
}

// round 3
// speedup vs baseline: 2.0282x; 2.0282x over previous
#include <cuda_runtime.h>
#include <cstdint>
#include <math.h>

#define Bsz   4096
#define Dd    256
#define Ccls  10
#define Nrows 8192
#define TILES 64          // 8192 / 128
#define NBLK  2080        // 64*65/2 triangular tiles

#define STR   40          // smem row stride in floats (2-way max conflict)

// ===================== device scratch ====================================
__device__ float g_sq[Nrows];
__device__ float g_vecsum[Dd];
__device__ float g_sumsq;
__device__ float g_ssum[Ccls];
__device__ float g_tsum[Ccls];
__device__ int   g_cnt[Ccls];
__device__ float g_sscale[Ccls];
__device__ float g_tscale[Ccls];   // carries minus sign for target rows
__device__ float g_expC;           // 1/(4*bw_raw)
__device__ float g_invcount;

// ---------------- helpers -------------------------------------------------
__device__ __forceinline__ uint32_t f2tf32(float v) {
    uint32_t u;
    asm("cvt.rna.tf32.f32 %0, %1;" : "=r"(u) : "f"(v));
    return u;
}
__device__ __forceinline__ void mma_tf32(float* d, const uint32_t* a, const uint32_t* b) {
    asm volatile(
        "mma.sync.aligned.m16n8k8.row.col.f32.tf32.tf32.f32 "
        "{%0,%1,%2,%3}, {%4,%5,%6,%7}, {%8,%9}, {%0,%1,%2,%3};"
        : "+f"(d[0]), "+f"(d[1]), "+f"(d[2]), "+f"(d[3])
        : "r"(a[0]), "r"(a[1]), "r"(a[2]), "r"(a[3]), "r"(b[0]), "r"(b[1]));
}

// ---------------- kernel 0: zero accumulators + output -------------------
__global__ void k_zero(float* out) {
    int t = threadIdx.x;
    if (t < Dd)   g_vecsum[t] = 0.f;
    if (t < Ccls) { g_ssum[t] = 0.f; g_tsum[t] = 0.f; g_cnt[t] = 0; }
    if (t == 0)   { g_sumsq = 0.f; out[0] = 0.f; }
}

// ---------------- kernel 1: label/logit column stats ----------------------
__global__ void k_stats(const float* __restrict__ slab,
                        const float* __restrict__ tlog) {
    __shared__ float sp[Ccls], tp[Ccls];
    __shared__ int   cp[Ccls];
    int t = threadIdx.x;
    if (t < Ccls) { sp[t] = 0.f; tp[t] = 0.f; cp[t] = 0; }
    __syncthreads();
    int r = blockIdx.x * 256 + t;
    float best = -1.f; int bidx = 0;
    #pragma unroll
    for (int c = 0; c < Ccls; c++) {
        float sv = slab[(size_t)r * Ccls + c];
        float tv = tlog[(size_t)r * Ccls + c];
        atomicAdd(&sp[c], sv);
        atomicAdd(&tp[c], tv);
        if (tv > best) { best = tv; bidx = c; }
    }
    atomicAdd(&cp[bidx], 1);
    __syncthreads();
    if (t < Ccls) {
        atomicAdd(&g_ssum[t], sp[t]);
        atomicAdd(&g_tsum[t], tp[t]);
        atomicAdd(&g_cnt[t],  cp[t]);
    }
}

// ---------------- kernel 2: fused row norms + column sums -----------------
__global__ void k_row(const float* __restrict__ src,
                      const float* __restrict__ tgt) {
    __shared__ float scol[8][256];
    __shared__ float bs[8];
    int w = threadIdx.x >> 5, lane = threadIdx.x & 31;
    #pragma unroll
    for (int i = 0; i < 8; i++) scol[w][lane + 32 * i] = 0.f;
    float wsq = 0.f;
    #pragma unroll
    for (int k = 0; k < 4; k++) {
        int row = blockIdx.x * 32 + w * 4 + k;
        const float* p = (row < Bsz) ? src + (size_t)row * Dd
                                     : tgt + (size_t)(row - Bsz) * Dd;
        float s = 0.f;
        #pragma unroll
        for (int i = 0; i < 8; i++) {
            float v = p[lane + 32 * i];
            s += v * v;
            scol[w][lane + 32 * i] += v;
        }
        #pragma unroll
        for (int o = 16; o; o >>= 1) s += __shfl_xor_sync(0xffffffffu, s, o);
        if (lane == 0) { g_sq[row] = s; wsq += s; }
    }
    if (lane == 0) bs[w] = wsq;
    __syncthreads();
    int t = threadIdx.x;
    float cs = 0.f;
    #pragma unroll
    for (int ww = 0; ww < 8; ww++) cs += scol[ww][t];
    atomicAdd(&g_vecsum[t], cs);
    if (t == 0) {
        float tot = 0.f;
        #pragma unroll
        for (int i = 0; i < 8; i++) tot += bs[i];
        atomicAdd(&g_sumsq, tot);
    }
}

// ---------------- kernel 3: finalize scales / bandwidth -------------------
__global__ void k_final() {
    int t = threadIdx.x;
    __shared__ float red[256];
    if (t < Ccls) {
        float s = g_ssum[t];
        int   c = g_cnt[t];
        bool mask = (s > 0.f) && (c > 0);
        g_sscale[t] = mask ? (1.f / s) : 0.f;
        float te = g_tsum[t]; te = (te == 0.f) ? 100.f : te;
        g_tscale[t] = mask ? (-1.f / te) : 0.f;
    }
    float v = g_vecsum[t];
    red[t] = v * v;
    __syncthreads();
    for (int s = 128; s; s >>= 1) { if (t < s) red[t] += red[t + s]; __syncthreads(); }
    if (t == 0) {
        int count = 0;
        for (int c = 0; c < Ccls; c++)
            if (g_ssum[c] > 0.f && g_cnt[c] > 0) count++;
        float VV = red[0];
        float S  = g_sumsq;
        float sum_l2 = 2.f * (float)Nrows * S - 2.f * VV;
        float nf = (float)Nrows;
        float bw_raw = sum_l2 / (nf * nf - nf);
        g_expC = 1.f / (4.f * bw_raw);
        g_invcount = (count > 0) ? 1.f / (float)count : 0.f;
    }
}

// ---------------- kernel 4: tf32 mma.sync pairwise GEMM + epilogue --------
// 128x128 tile per block (triangular grid), 256 threads = 8 warps (2x4),
// warp tile 64x32, m16n8k8 tf32, K chunked by 32 through smem.
// Smem k layout per 8-octet: slot = 2*(k&3) + (k>>2)  (same perm both sides,
// dot invariant) so (t, t+4) fragment pairs are contiguous -> LDS.64.
#define OFF_A   0
#define OFF_B   (128 * STR * 4)
#define OFF_UP  (2 * 128 * STR * 4)
#define OFF_UQ  (OFF_UP + Ccls * 128 * 4)
#define OFF_SQP (OFF_UQ + Ccls * 128 * 4)
#define OFF_SQQ (OFF_SQP + 512)
#define OFF_RED (OFF_SQQ + 512)
#define SMEM_DYN (OFF_RED + 64)

__global__ void __launch_bounds__(256, 2) k_main(
    const float* __restrict__ src, const float* __restrict__ tgt,
    const float* __restrict__ slab, const float* __restrict__ tlog,
    float* __restrict__ out)
{
    extern __shared__ char sm[];
    float* smA = (float*)(sm + OFF_A);
    float* smB = (float*)(sm + OFF_B);
    float* uPs = (float*)(sm + OFF_UP);   // [10][128]
    float* uQs = (float*)(sm + OFF_UQ);   // [10][128]
    float* sqP = (float*)(sm + OFF_SQP);
    float* sqQ = (float*)(sm + OFF_SQQ);
    float* red = (float*)(sm + OFF_RED);

    int tid = threadIdx.x;
    int w = tid >> 5, lane = tid & 31;
    int g = lane >> 2, t4 = lane & 3;
    int wr = w >> 2, wc = w & 3;          // warp grid 2 x 4
    int b = blockIdx.x;

    // triangular decode (bi <= bj)
    int bi = (int)((2.f * TILES + 1.f -
                    sqrtf((float)((2 * TILES + 1) * (2 * TILES + 1) - 8 * b))) * 0.5f);
    if (bi < 0) bi = 0; if (bi > TILES - 1) bi = TILES - 1;
    while (bi > 0 && bi * TILES - bi * (bi - 1) / 2 > b) bi--;
    while ((bi + 1) * TILES - (bi + 1) * bi / 2 <= b) bi++;
    int bj = bi + (b - (bi * TILES - bi * (bi - 1) / 2));

    int p0 = bi * 128, q0 = bj * 128;
    const float* Ab = (p0 < Bsz) ? src + (size_t)p0 * Dd : tgt + (size_t)(p0 - Bsz) * Dd;
    const float* Bb = (q0 < Bsz) ? src + (size_t)q0 * Dd : tgt + (size_t)(q0 - Bsz) * Dd;

    // ---- load u vectors (scaled, sign-carrying) + squared norms ----
    if (tid < 128) {
        int p = p0 + tid;
        sqP[tid] = g_sq[p];
        if (p < Bsz) {
            #pragma unroll
            for (int c = 0; c < Ccls; c++)
                uPs[c * 128 + tid] = slab[(size_t)p * Ccls + c] * g_sscale[c];
        } else {
            #pragma unroll
            for (int c = 0; c < Ccls; c++)
                uPs[c * 128 + tid] = tlog[(size_t)(p - Bsz) * Ccls + c] * g_tscale[c];
        }
    } else {
        int j = tid - 128;
        int q = q0 + j;
        sqQ[j] = g_sq[q];
        if (q < Bsz) {
            #pragma unroll
            for (int c = 0; c < Ccls; c++)
                uQs[c * 128 + j] = slab[(size_t)q * Ccls + c] * g_sscale[c];
        } else {
            #pragma unroll
            for (int c = 0; c < Ccls; c++)
                uQs[c * 128 + j] = tlog[(size_t)(q - Bsz) * Ccls + c] * g_tscale[c];
        }
    }

    float acc[16][4];
    #pragma unroll
    for (int i = 0; i < 16; i++)
        #pragma unroll
        for (int j = 0; j < 4; j++) acc[i][j] = 0.f;

    // ---- mainloop: 8 K-chunks of 32 ----
    for (int ch = 0; ch < 8; ch++) {
        __syncthreads();
        #pragma unroll
        for (int i = 0; i < 4; i++) {
            int gg = tid + 256 * i;               // 0..1023
            int row = gg >> 3, kq = gg & 7;
            float4 va = *(const float4*)(Ab + (size_t)row * Dd + ch * 32 + kq * 4);
            float4 vb = *(const float4*)(Bb + (size_t)row * Dd + ch * 32 + kq * 4);
            int base = row * STR + (kq >> 1) * 8 + (kq & 1);
            uint32_t* da = (uint32_t*)smA;
            uint32_t* db = (uint32_t*)smB;
            da[base + 0] = f2tf32(va.x); da[base + 2] = f2tf32(va.y);
            da[base + 4] = f2tf32(va.z); da[base + 6] = f2tf32(va.w);
            db[base + 0] = f2tf32(vb.x); db[base + 2] = f2tf32(vb.y);
            db[base + 4] = f2tf32(vb.z); db[base + 6] = f2tf32(vb.w);
        }
        __syncthreads();

        #pragma unroll
        for (int ks = 0; ks < 4; ks++) {
            uint32_t afr[4][4];                   // per m-tile: a0,a1,a2,a3
            #pragma unroll
            for (int mi = 0; mi < 4; mi++) {
                int r0 = wr * 64 + mi * 16 + g;
                float2 lo = *(float2*)&smA[r0 * STR + ks * 8 + 2 * t4];
                float2 hi = *(float2*)&smA[(r0 + 8) * STR + ks * 8 + 2 * t4];
                afr[mi][0] = __float_as_uint(lo.x);  // a0: (g, t)
                afr[mi][1] = __float_as_uint(hi.x);  // a1: (g+8, t)
                afr[mi][2] = __float_as_uint(lo.y);  // a2: (g, t+4)
                afr[mi][3] = __float_as_uint(hi.y);  // a3: (g+8, t+4)
            }
            uint32_t bfr[4][2];
            #pragma unroll
            for (int ni = 0; ni < 4; ni++) {
                int c0 = wc * 32 + ni * 8 + g;
                float2 bv = *(float2*)&smB[c0 * STR + ks * 8 + 2 * t4];
                bfr[ni][0] = __float_as_uint(bv.x);  // b0: (k=t,   n=g)
                bfr[ni][1] = __float_as_uint(bv.y);  // b1: (k=t+4, n=g)
            }
            #pragma unroll
            for (int mi = 0; mi < 4; mi++)
                #pragma unroll
                for (int ni = 0; ni < 4; ni++)
                    mma_tf32(acc[mi * 4 + ni], afr[mi], bfr[ni]);
        }
    }
    __syncthreads();

    // ---- epilogue ----
    const float Ce = g_expC;
    const float scale = g_invcount * ((bi == bj) ? 1.f : 2.f);
    float partial = 0.f;

    #pragma unroll
    for (int mi = 0; mi < 4; mi++) {
        int r0 = wr * 64 + mi * 16 + g;
        int r1 = r0 + 8;
        float up0[Ccls], up1[Ccls];
        #pragma unroll
        for (int c = 0; c < Ccls; c++) {
            up0[c] = uPs[c * 128 + r0];
            up1[c] = uPs[c * 128 + r1];
        }
        float sp0 = sqP[r0], sp1 = sqP[r1];
        #pragma unroll
        for (int ni = 0; ni < 4; ni++) {
            float* a = acc[mi * 4 + ni];
            int cb = wc * 32 + ni * 8 + 2 * t4;
            float2 sv = *(float2*)&sqQ[cb];
            float w00 = 0.f, w01 = 0.f, w10 = 0.f, w11 = 0.f;
            #pragma unroll
            for (int c = 0; c < Ccls; c++) {
                float2 uq = *(float2*)&uQs[c * 128 + cb];
                w00 = fmaf(up0[c], uq.x, w00);
                w01 = fmaf(up0[c], uq.y, w01);
                w10 = fmaf(up1[c], uq.x, w10);
                w11 = fmaf(up1[c], uq.y, w11);
            }
            float l2, z, z2, z4, z8;
            l2 = fmaxf(sp0 + sv.x - 2.f * a[0], 0.f);
            z = __expf(-l2 * Ce); z2 = z * z; z4 = z2 * z2; z8 = z4 * z4;
            partial = fmaf(w00, z + z2 + z4 + z8 + z8 * z8, partial);
            l2 = fmaxf(sp0 + sv.y - 2.f * a[1], 0.f);
            z = __expf(-l2 * Ce); z2 = z * z; z4 = z2 * z2; z8 = z4 * z4;
            partial = fmaf(w01, z + z2 + z4 + z8 + z8 * z8, partial);
            l2 = fmaxf(sp1 + sv.x - 2.f * a[2], 0.f);
            z = __expf(-l2 * Ce); z2 = z * z; z4 = z2 * z2; z8 = z4 * z4;
            partial = fmaf(w10, z + z2 + z4 + z8 + z8 * z8, partial);
            l2 = fmaxf(sp1 + sv.y - 2.f * a[3], 0.f);
            z = __expf(-l2 * Ce); z2 = z * z; z4 = z2 * z2; z8 = z4 * z4;
            partial = fmaf(w11, z + z2 + z4 + z8 + z8 * z8, partial);
        }
    }
    partial *= scale;

    #pragma unroll
    for (int o = 16; o; o >>= 1) partial += __shfl_xor_sync(0xffffffffu, partial, o);
    if (lane == 0) red[w] = partial;
    __syncthreads();
    if (tid == 0) {
        float s = 0.f;
        #pragma unroll
        for (int i = 0; i < 8; i++) s += red[i];
        atomicAdd(out, s);
    }
}

// ---------------- launcher ------------------------------------------------
extern "C" void kernel_launch(void* const* d_in, const int* in_sizes, int n_in,
                              void* d_out, int out_size) {
    const float* src  = (const float*)d_in[0];
    const float* tgt  = (const float*)d_in[1];
    const float* slab = (const float*)d_in[2];
    const float* tlog = (const float*)d_in[3];
    float* out = (float*)d_out;

    static int configured = 0;
    if (!configured) {
        cudaFuncSetAttribute(k_main, cudaFuncAttributeMaxDynamicSharedMemorySize, SMEM_DYN);
        configured = 1;
    }

    k_zero<<<1, 256>>>(out);
    k_stats<<<Bsz / 256, 256>>>(slab, tlog);
    k_row<<<Nrows / 32, 256>>>(src, tgt);
    k_final<<<1, 256>>>();
    k_main<<<NBLK, 256, SMEM_DYN>>>(src, tgt, slab, tlog, out);
}

// round 4
// speedup vs baseline: 2.4515x; 1.2087x over previous
#include <cuda_runtime.h>
#include <cstdint>
#include <math.h>

#define Bsz   4096
#define Dd    256
#define Ccls  10
#define Nrows 8192
#define TILES 64          // 8192 / 128
#define NBLK  2080        // 64*65/2 triangular tiles
#define USTR  132         // class-major u stride (floats)

// ===================== device scratch ====================================
__device__ __align__(16) float g_xr[Nrows * Dd];  // tf32-rounded copy (8MB)
__device__ float g_sq[Nrows];
__device__ float g_spart[16][Ccls];
__device__ float g_tpart[16][Ccls];
__device__ int   g_cpart[16][Ccls];
__device__ float g_vpart[256][256];   // per-block column sums
__device__ float g_qpart[256];        // per-block sum of squared norms
__device__ float g_sscale[Ccls];
__device__ float g_tscale[Ccls];      // carries minus sign for target rows
__device__ float g_expC;              // 1/(4*bw_raw)
__device__ float g_invcount;

// ---------------- helpers -------------------------------------------------
__device__ __forceinline__ uint32_t f2tf32(float v) {
    uint32_t u;
    asm("cvt.rna.tf32.f32 %0, %1;" : "=r"(u) : "f"(v));
    return u;
}
__device__ __forceinline__ void mma_tf32(float* d, const uint32_t* a, const uint32_t* b) {
    asm volatile(
        "mma.sync.aligned.m16n8k8.row.col.f32.tf32.tf32.f32 "
        "{%0,%1,%2,%3}, {%4,%5,%6,%7}, {%8,%9}, {%0,%1,%2,%3};"
        : "+f"(d[0]), "+f"(d[1]), "+f"(d[2]), "+f"(d[3])
        : "r"(a[0]), "r"(a[1]), "r"(a[2]), "r"(a[3]), "r"(b[0]), "r"(b[1]));
}
__device__ __forceinline__ uint32_t smem_u32(const void* p) {
    return (uint32_t)__cvta_generic_to_shared(p);
}
#define CP_ASYNC16(dst, src) \
    asm volatile("cp.async.ca.shared.global [%0], [%1], 16;" :: "r"(dst), "l"(src))
#define CP_COMMIT() asm volatile("cp.async.commit_group;")
#define CP_WAIT(n)  asm volatile("cp.async.wait_group %0;" :: "n"(n))

// ---------------- kernel 1: label/logit column stats (partials) ----------
__global__ void k_stats(const float* __restrict__ slab,
                        const float* __restrict__ tlog) {
    __shared__ float sp[Ccls], tp[Ccls];
    __shared__ int   cp[Ccls];
    int t = threadIdx.x;
    if (t < Ccls) { sp[t] = 0.f; tp[t] = 0.f; cp[t] = 0; }
    __syncthreads();
    int r = blockIdx.x * 256 + t;
    float best = -1.f; int bidx = 0;
    #pragma unroll
    for (int c = 0; c < Ccls; c++) {
        float sv = slab[(size_t)r * Ccls + c];
        float tv = tlog[(size_t)r * Ccls + c];
        atomicAdd(&sp[c], sv);
        atomicAdd(&tp[c], tv);
        if (tv > best) { best = tv; bidx = c; }
    }
    atomicAdd(&cp[bidx], 1);
    __syncthreads();
    if (t < Ccls) {
        g_spart[blockIdx.x][t] = sp[t];
        g_tpart[blockIdx.x][t] = tp[t];
        g_cpart[blockIdx.x][t] = cp[t];
    }
}

// ---------------- kernel 2: row norms + col sums + tf32 pre-round ---------
// grid 256 x 256; block = 32 rows, warp = 4 rows (coalesced).
__global__ void k_row(const float* __restrict__ src,
                      const float* __restrict__ tgt) {
    __shared__ float scol[8][256];
    __shared__ float bs[8];
    int w = threadIdx.x >> 5, lane = threadIdx.x & 31;
    #pragma unroll
    for (int i = 0; i < 8; i++) scol[w][lane + 32 * i] = 0.f;
    float wsq = 0.f;
    #pragma unroll
    for (int k = 0; k < 4; k++) {
        int row = blockIdx.x * 32 + w * 4 + k;
        const float* p = (row < Bsz) ? src + (size_t)row * Dd
                                     : tgt + (size_t)(row - Bsz) * Dd;
        float s = 0.f;
        #pragma unroll
        for (int i = 0; i < 8; i++) {
            float v = p[lane + 32 * i];
            s += v * v;
            scol[w][lane + 32 * i] += v;
            g_xr[(size_t)row * Dd + lane + 32 * i] = __uint_as_float(f2tf32(v));
        }
        #pragma unroll
        for (int o = 16; o; o >>= 1) s += __shfl_xor_sync(0xffffffffu, s, o);
        if (lane == 0) { g_sq[row] = s; wsq += s; }
    }
    if (lane == 0) bs[w] = wsq;
    __syncthreads();
    int t = threadIdx.x;
    float cs = 0.f;
    #pragma unroll
    for (int ww = 0; ww < 8; ww++) cs += scol[ww][t];
    g_vpart[blockIdx.x][t] = cs;
    if (t == 0) {
        float tot = 0.f;
        #pragma unroll
        for (int i = 0; i < 8; i++) tot += bs[i];
        g_qpart[blockIdx.x] = tot;
    }
}

// ---------------- kernel 3: finalize scales / bandwidth / zero out --------
__global__ void k_final(float* out) {
    int t = threadIdx.x;
    __shared__ float red[256];
    __shared__ float ssumS[Ccls];
    __shared__ int   cntS[Ccls];
    if (t < Ccls) {
        float ss = 0.f, ts = 0.f; int cc = 0;
        #pragma unroll
        for (int b = 0; b < 16; b++) {
            ss += g_spart[b][t];
            ts += g_tpart[b][t];
            cc += g_cpart[b][t];
        }
        ssumS[t] = ss; cntS[t] = cc;
        bool mask = (ss > 0.f) && (cc > 0);
        g_sscale[t] = mask ? (1.f / ss) : 0.f;
        float te = (ts == 0.f) ? 100.f : ts;
        g_tscale[t] = mask ? (-1.f / te) : 0.f;
    }
    // column-sum reduce: v[t] = sum_b vpart[b][t]
    float v = 0.f;
    #pragma unroll 8
    for (int b = 0; b < 256; b++) v += g_vpart[b][t];
    red[t] = v * v;
    __syncthreads();
    for (int s = 128; s; s >>= 1) { if (t < s) red[t] += red[t + s]; __syncthreads(); }
    float VV = red[0];
    __syncthreads();
    red[t] = g_qpart[t];
    __syncthreads();
    for (int s = 128; s; s >>= 1) { if (t < s) red[t] += red[t + s]; __syncthreads(); }
    if (t == 0) {
        int count = 0;
        for (int c = 0; c < Ccls; c++)
            if (ssumS[c] > 0.f && cntS[c] > 0) count++;
        float S = red[0];
        float sum_l2 = 2.f * (float)Nrows * S - 2.f * VV;
        float nf = (float)Nrows;
        float bw_raw = sum_l2 / (nf * nf - nf);
        g_expC = 1.f / (4.f * bw_raw);
        g_invcount = (count > 0) ? 1.f / (float)count : 0.f;
        out[0] = 0.f;
    }
}

// ---------------- kernel 4: tf32 mma pairwise GEMM + MMD epilogue ---------
// 128x128 tile (triangular grid), 256 threads = 8 warps (2x4), warp tile
// 64x32, m16n8k8 tf32. Operands: XOR-swizzled smem rows of 32 floats
// (16B chunk c stored at c ^ (row&7)); cp.async double-buffered from g_xr.
#define OFF_BUF 0                       // 2 bufs x (A 16KB + B 16KB)
#define OFF_UP  65536                   // [10][USTR] floats
#define OFF_UQ  (OFF_UP + Ccls * USTR * 4)
#define OFF_SQP (OFF_UQ + Ccls * USTR * 4)
#define OFF_SQQ (OFF_SQP + 512)
#define OFF_RED (OFF_SQQ + 512)
#define SMEM_DYN (OFF_RED + 64)

__global__ void __launch_bounds__(256, 2) k_main(
    const float* __restrict__ slab, const float* __restrict__ tlog,
    float* __restrict__ out)
{
    extern __shared__ char sm[];
    float* uPs = (float*)(sm + OFF_UP);   // [10][USTR]
    float* uQs = (float*)(sm + OFF_UQ);
    float* sqP = (float*)(sm + OFF_SQP);
    float* sqQ = (float*)(sm + OFF_SQQ);
    float* red = (float*)(sm + OFF_RED);
    uint32_t smb = smem_u32(sm);

    int tid = threadIdx.x;
    int w = tid >> 5, lane = tid & 31;
    int g = lane >> 2, t4 = lane & 3;
    int wr = w >> 2, wc = w & 3;          // warp grid 2 x 4
    int b = blockIdx.x;

    // triangular decode (bi <= bj)
    int bi = (int)((2.f * TILES + 1.f -
                    sqrtf((float)((2 * TILES + 1) * (2 * TILES + 1) - 8 * b))) * 0.5f);
    if (bi < 0) bi = 0; if (bi > TILES - 1) bi = TILES - 1;
    while (bi > 0 && bi * TILES - bi * (bi - 1) / 2 > b) bi--;
    while ((bi + 1) * TILES - (bi + 1) * bi / 2 <= b) bi++;
    int bj = bi + (b - (bi * TILES - bi * (bi - 1) / 2));

    int p0 = bi * 128, q0 = bj * 128;
    const float* xA = g_xr + (size_t)p0 * Dd;
    const float* xB = g_xr + (size_t)q0 * Dd;

    // ---- stage u vectors (scaled, sign-carrying) + squared norms ----
    if (tid < 128) {
        int p = p0 + tid;
        sqP[tid] = g_sq[p];
        if (p < Bsz) {
            #pragma unroll
            for (int c = 0; c < Ccls; c++)
                uPs[c * USTR + tid] = slab[(size_t)p * Ccls + c] * g_sscale[c];
        } else {
            #pragma unroll
            for (int c = 0; c < Ccls; c++)
                uPs[c * USTR + tid] = tlog[(size_t)(p - Bsz) * Ccls + c] * g_tscale[c];
        }
    } else {
        int j = tid - 128;
        int q = q0 + j;
        sqQ[j] = g_sq[q];
        if (q < Bsz) {
            #pragma unroll
            for (int c = 0; c < Ccls; c++)
                uQs[c * USTR + j] = slab[(size_t)q * Ccls + c] * g_sscale[c];
        } else {
            #pragma unroll
            for (int c = 0; c < Ccls; c++)
                uQs[c * USTR + j] = tlog[(size_t)(q - Bsz) * Ccls + c] * g_tscale[c];
        }
    }

    // per-thread prefetch coordinates: 4 (row, chunk) pairs per operand
    int prow[4], pch[4];
    uint32_t pdst[4];
    #pragma unroll
    for (int i = 0; i < 4; i++) {
        int gg = tid + 256 * i;               // 0..1023
        prow[i] = gg >> 3;
        pch[i]  = gg & 7;
        pdst[i] = (uint32_t)(prow[i] * 128 + ((pch[i] ^ (prow[i] & 7)) * 16));
    }

    // prefetch chunk 0 into buf 0
    {
        uint32_t sA = smb + OFF_BUF;
        uint32_t sB = sA + 16384u;
        #pragma unroll
        for (int i = 0; i < 4; i++) {
            const float* srcA = xA + (size_t)prow[i] * Dd + pch[i] * 4;
            const float* srcB = xB + (size_t)prow[i] * Dd + pch[i] * 4;
            CP_ASYNC16(sA + pdst[i], srcA);
            CP_ASYNC16(sB + pdst[i], srcB);
        }
        CP_COMMIT();
    }

    float acc[16][4];
    #pragma unroll
    for (int i = 0; i < 16; i++)
        #pragma unroll
        for (int j = 0; j < 4; j++) acc[i][j] = 0.f;

    // ---- mainloop: 8 K-chunks of 32, double buffered ----
    for (int ch = 0; ch < 8; ch++) {
        int buf = ch & 1;
        if (ch < 7) {
            uint32_t sA = smb + OFF_BUF + (buf ^ 1) * 32768u;
            uint32_t sB = sA + 16384u;
            int ko = (ch + 1) * 32;
            #pragma unroll
            for (int i = 0; i < 4; i++) {
                const float* srcA = xA + (size_t)prow[i] * Dd + ko + pch[i] * 4;
                const float* srcB = xB + (size_t)prow[i] * Dd + ko + pch[i] * 4;
                CP_ASYNC16(sA + pdst[i], srcA);
                CP_ASYNC16(sB + pdst[i], srcB);
            }
            CP_COMMIT();
            CP_WAIT(1);
        } else {
            CP_WAIT(0);
        }
        __syncthreads();

        const uint32_t* AS = (const uint32_t*)(sm + OFF_BUF + buf * 32768);
        const uint32_t* BS = AS + 4096;

        #pragma unroll
        for (int ks = 0; ks < 4; ks++) {
            int ca = ((2 * ks) ^ g) * 4 + t4;     // k = ks*8 + t4
            int cb = ca ^ 4;                       // k = ks*8 + t4 + 4
            uint32_t afr[4][4];
            #pragma unroll
            for (int mi = 0; mi < 4; mi++) {
                int rA = (wr * 64 + mi * 16 + g) * 32;
                afr[mi][0] = AS[rA + ca];
                afr[mi][1] = AS[rA + 256 + ca];    // row + 8
                afr[mi][2] = AS[rA + cb];
                afr[mi][3] = AS[rA + 256 + cb];
            }
            uint32_t bfr[4][2];
            #pragma unroll
            for (int ni = 0; ni < 4; ni++) {
                int rB = (wc * 32 + ni * 8 + g) * 32;
                bfr[ni][0] = BS[rB + ca];
                bfr[ni][1] = BS[rB + cb];
            }
            #pragma unroll
            for (int mi = 0; mi < 4; mi++)
                #pragma unroll
                for (int ni = 0; ni < 4; ni++)
                    mma_tf32(acc[mi * 4 + ni], afr[mi], bfr[ni]);
        }
        __syncthreads();
    }

    // ---- epilogue ----
    const float Ce = g_expC;
    const float scale = g_invcount * ((bi == bj) ? 1.f : 2.f);
    float partial = 0.f;

    #pragma unroll
    for (int mi = 0; mi < 4; mi++) {
        int r0 = wr * 64 + mi * 16 + g;
        int r1 = r0 + 8;
        float up0[Ccls], up1[Ccls];
        #pragma unroll
        for (int c = 0; c < Ccls; c++) {
            up0[c] = uPs[c * USTR + r0];
            up1[c] = uPs[c * USTR + r1];
        }
        float sp0 = sqP[r0], sp1 = sqP[r1];
        #pragma unroll
        for (int ni = 0; ni < 4; ni++) {
            float* a = acc[mi * 4 + ni];
            int cbx = wc * 32 + ni * 8 + 2 * t4;
            float2 sv = *(float2*)&sqQ[cbx];
            float w00 = 0.f, w01 = 0.f, w10 = 0.f, w11 = 0.f;
            #pragma unroll
            for (int c = 0; c < Ccls; c++) {
                float2 uq = *(float2*)&uQs[c * USTR + cbx];
                w00 = fmaf(up0[c], uq.x, w00);
                w01 = fmaf(up0[c], uq.y, w01);
                w10 = fmaf(up1[c], uq.x, w10);
                w11 = fmaf(up1[c], uq.y, w11);
            }
            float l2, z, z2, z4, z8;
            l2 = fmaxf(sp0 + sv.x - 2.f * a[0], 0.f);
            z = __expf(-l2 * Ce); z2 = z * z; z4 = z2 * z2; z8 = z4 * z4;
            partial = fmaf(w00, z + z2 + z4 + z8 + z8 * z8, partial);
            l2 = fmaxf(sp0 + sv.y - 2.f * a[1], 0.f);
            z = __expf(-l2 * Ce); z2 = z * z; z4 = z2 * z2; z8 = z4 * z4;
            partial = fmaf(w01, z + z2 + z4 + z8 + z8 * z8, partial);
            l2 = fmaxf(sp1 + sv.x - 2.f * a[2], 0.f);
            z = __expf(-l2 * Ce); z2 = z * z; z4 = z2 * z2; z8 = z4 * z4;
            partial = fmaf(w10, z + z2 + z4 + z8 + z8 * z8, partial);
            l2 = fmaxf(sp1 + sv.y - 2.f * a[3], 0.f);
            z = __expf(-l2 * Ce); z2 = z * z; z4 = z2 * z2; z8 = z4 * z4;
            partial = fmaf(w11, z + z2 + z4 + z8 + z8 * z8, partial);
        }
    }
    partial *= scale;

    #pragma unroll
    for (int o = 16; o; o >>= 1) partial += __shfl_xor_sync(0xffffffffu, partial, o);
    if (lane == 0) red[w] = partial;
    __syncthreads();
    if (tid == 0) {
        float s = 0.f;
        #pragma unroll
        for (int i = 0; i < 8; i++) s += red[i];
        atomicAdd(out, s);
    }
}

// ---------------- launcher ------------------------------------------------
extern "C" void kernel_launch(void* const* d_in, const int* in_sizes, int n_in,
                              void* d_out, int out_size) {
    const float* src  = (const float*)d_in[0];
    const float* tgt  = (const float*)d_in[1];
    const float* slab = (const float*)d_in[2];
    const float* tlog = (const float*)d_in[3];
    float* out = (float*)d_out;

    static int configured = 0;
    if (!configured) {
        cudaFuncSetAttribute(k_main, cudaFuncAttributeMaxDynamicSharedMemorySize, SMEM_DYN);
        configured = 1;
    }

    k_stats<<<Bsz / 256, 256>>>(slab, tlog);
    k_row<<<Nrows / 32, 256>>>(src, tgt);
    k_final<<<1, 256>>>(out);
    k_main<<<NBLK, 256, SMEM_DYN>>>(slab, tlog, out);
}

// round 5
// speedup vs baseline: 2.9237x; 1.1926x over previous
#include <cuda_runtime.h>
#include <cstdint>
#include <math.h>

#define Bsz   4096
#define Dd    256
#define Ccls  10
#define Nrows 8192
#define TILES 64          // 8192 / 128
#define NBLK  2080        // 64*65/2 triangular tiles
#define USTR  132         // class-major u stride (floats)

// ===================== device scratch ====================================
__device__ __align__(16) float g_xr[Nrows * Dd];  // tf32-rounded copy (8MB)
__device__ float g_sq[Nrows];
__device__ float g_spart[128][Ccls];
__device__ float g_tpart[128][Ccls];
__device__ int   g_cpart[128][Ccls];
__device__ float g_vpart[256][256];   // per-block column sums
__device__ float g_qpart[256];        // per-block sum of squared norms
__device__ float g_sscale[Ccls];
__device__ float g_tscale[Ccls];      // carries minus sign for target rows
__device__ float g_expC;              // 1/(4*bw_raw)
__device__ float g_invcount;
__device__ unsigned g_ctr;            // last-block counter (monotonic)

// ---------------- helpers -------------------------------------------------
__device__ __forceinline__ uint32_t f2tf32(float v) {
    uint32_t u;
    asm("cvt.rna.tf32.f32 %0, %1;" : "=r"(u) : "f"(v));
    return u;
}
__device__ __forceinline__ void mma_tf32(float* d, const uint32_t* a, const uint32_t* b) {
    asm volatile(
        "mma.sync.aligned.m16n8k8.row.col.f32.tf32.tf32.f32 "
        "{%0,%1,%2,%3}, {%4,%5,%6,%7}, {%8,%9}, {%0,%1,%2,%3};"
        : "+f"(d[0]), "+f"(d[1]), "+f"(d[2]), "+f"(d[3])
        : "r"(a[0]), "r"(a[1]), "r"(a[2]), "r"(a[3]), "r"(b[0]), "r"(b[1]));
}
__device__ __forceinline__ void ldsm_x4(uint32_t* r, uint32_t addr) {
    asm volatile("ldmatrix.sync.aligned.m8n8.x4.shared.b16 {%0,%1,%2,%3}, [%4];"
        : "=r"(r[0]), "=r"(r[1]), "=r"(r[2]), "=r"(r[3]) : "r"(addr));
}
__device__ __forceinline__ void ldsm_x2(uint32_t* r, uint32_t addr) {
    asm volatile("ldmatrix.sync.aligned.m8n8.x2.shared.b16 {%0,%1}, [%2];"
        : "=r"(r[0]), "=r"(r[1]) : "r"(addr));
}
__device__ __forceinline__ uint32_t smem_u32(const void* p) {
    return (uint32_t)__cvta_generic_to_shared(p);
}
#define CP_ASYNC16(dst, src) \
    asm volatile("cp.async.ca.shared.global [%0], [%1], 16;" :: "r"(dst), "l"(src))
#define CP_COMMIT() asm volatile("cp.async.commit_group;")
#define CP_WAIT(n)  asm volatile("cp.async.wait_group %0;" :: "n"(n))

// ---------------- kernel 1: rows + stats + (last block) finalize ----------
// grid 256 x 256; block = 32 rows. Warp 0 additionally does label/logit
// stats for its 32 rows. The last block to finish computes scales/bandwidth.
__global__ void k_row(const float* __restrict__ src,
                      const float* __restrict__ tgt,
                      const float* __restrict__ slab,
                      const float* __restrict__ tlog,
                      float* __restrict__ out) {
    __shared__ float scol[8][256];
    __shared__ float bs[8];
    __shared__ float sp10[Ccls];
    __shared__ int   cp10[Ccls];
    __shared__ int   lastFlag;
    int tid = threadIdx.x;
    int w = tid >> 5, lane = tid & 31;
    int bid = blockIdx.x;

    // ---- warp 0: label/logit column stats for this block's 32 rows ----
    if (w == 0) {
        if (lane < Ccls) { sp10[lane] = 0.f; cp10[lane] = 0; }
        __syncwarp();
        int r = bid * 32 + lane;
        if (bid < 128) {
            #pragma unroll
            for (int c = 0; c < Ccls; c++)
                atomicAdd(&sp10[c], slab[(size_t)r * Ccls + c]);
        } else {
            int rr = r - Bsz;
            float best = -1.f; int bx = 0;
            #pragma unroll
            for (int c = 0; c < Ccls; c++) {
                float tv = tlog[(size_t)rr * Ccls + c];
                atomicAdd(&sp10[c], tv);
                if (tv > best) { best = tv; bx = c; }
            }
            atomicAdd(&cp10[bx], 1);
        }
        __syncwarp();
        if (lane < Ccls) {
            if (bid < 128) g_spart[bid][lane] = sp10[lane];
            else { g_tpart[bid - 128][lane] = sp10[lane];
                   g_cpart[bid - 128][lane] = cp10[lane]; }
        }
    }

    // ---- row norms + column sums + tf32 pre-round (all warps) ----
    #pragma unroll
    for (int i = 0; i < 8; i++) scol[w][lane + 32 * i] = 0.f;
    float wsq = 0.f;
    #pragma unroll
    for (int k = 0; k < 4; k++) {
        int row = bid * 32 + w * 4 + k;
        const float* p = (row < Bsz) ? src + (size_t)row * Dd
                                     : tgt + (size_t)(row - Bsz) * Dd;
        float s = 0.f;
        #pragma unroll
        for (int i = 0; i < 8; i++) {
            float v = p[lane + 32 * i];
            s += v * v;
            scol[w][lane + 32 * i] += v;
            g_xr[(size_t)row * Dd + lane + 32 * i] = __uint_as_float(f2tf32(v));
        }
        #pragma unroll
        for (int o = 16; o; o >>= 1) s += __shfl_xor_sync(0xffffffffu, s, o);
        if (lane == 0) { g_sq[row] = s; wsq += s; }
    }
    if (lane == 0) bs[w] = wsq;
    __syncthreads();
    float cs = 0.f;
    #pragma unroll
    for (int ww = 0; ww < 8; ww++) cs += scol[ww][tid];
    g_vpart[bid][tid] = cs;
    if (tid == 0) {
        float tot = 0.f;
        #pragma unroll
        for (int i = 0; i < 8; i++) tot += bs[i];
        g_qpart[bid] = tot;
    }

    // ---- last block finalizes ----
    __threadfence();
    if (tid == 0) {
        unsigned old = atomicAdd(&g_ctr, 1u);
        lastFlag = (((old + 1u) & 255u) == 0u);
    }
    __syncthreads();
    if (!lastFlag) return;

    __shared__ float red[256];
    __shared__ float ssumS[Ccls];
    __shared__ int   cntS[Ccls];
    int t = tid;
    if (t < Ccls) {
        float ss = 0.f, ts = 0.f; int cc = 0;
        #pragma unroll 4
        for (int b2 = 0; b2 < 128; b2++) {
            ss += g_spart[b2][t];
            ts += g_tpart[b2][t];
            cc += g_cpart[b2][t];
        }
        ssumS[t] = ss; cntS[t] = cc;
        bool mask = (ss > 0.f) && (cc > 0);
        g_sscale[t] = mask ? (1.f / ss) : 0.f;
        float te = (ts == 0.f) ? 100.f : ts;
        g_tscale[t] = mask ? (-1.f / te) : 0.f;
    }
    float v = 0.f;
    #pragma unroll 8
    for (int b2 = 0; b2 < 256; b2++) v += g_vpart[b2][t];
    red[t] = v * v;
    __syncthreads();
    for (int s = 128; s; s >>= 1) { if (t < s) red[t] += red[t + s]; __syncthreads(); }
    float VV = red[0];
    __syncthreads();
    red[t] = g_qpart[t];
    __syncthreads();
    for (int s = 128; s; s >>= 1) { if (t < s) red[t] += red[t + s]; __syncthreads(); }
    if (t == 0) {
        int count = 0;
        for (int c = 0; c < Ccls; c++)
            if (ssumS[c] > 0.f && cntS[c] > 0) count++;
        float S = red[0];
        float sum_l2 = 2.f * (float)Nrows * S - 2.f * VV;
        float nf = (float)Nrows;
        float bw_raw = sum_l2 / (nf * nf - nf);
        g_expC = 1.f / (4.f * bw_raw);
        g_invcount = (count > 0) ? 1.f / (float)count : 0.f;
        out[0] = 0.f;
    }
}

// ---------------- kernel 2: tf32 mma pairwise GEMM + MMD epilogue ---------
// 128x128 tile (triangular grid), 256 threads = 8 warps (2x4), warp tile
// 64x32, m16n8k8 tf32. Operands in XOR-swizzled smem (16B chunk c at
// c ^ (row&7)); cp.async double-buffered; ldmatrix fragment loads with a
// ks-level software pipeline.
#define OFF_BUF 0                       // 2 bufs x (A 16KB + B 16KB)
#define OFF_UP  65536                   // [10][USTR] floats
#define OFF_UQ  (OFF_UP + Ccls * USTR * 4)
#define OFF_SQP (OFF_UQ + Ccls * USTR * 4)
#define OFF_SQQ (OFF_SQP + 512)
#define OFF_RED (OFF_SQQ + 512)
#define SMEM_DYN (OFF_RED + 64)

__global__ void __launch_bounds__(256, 2) k_main(
    const float* __restrict__ slab, const float* __restrict__ tlog,
    float* __restrict__ out)
{
    extern __shared__ char sm[];
    float* uPs = (float*)(sm + OFF_UP);   // [10][USTR]
    float* uQs = (float*)(sm + OFF_UQ);
    float* sqP = (float*)(sm + OFF_SQP);
    float* sqQ = (float*)(sm + OFF_SQQ);
    float* red = (float*)(sm + OFF_RED);
    uint32_t smb = smem_u32(sm);

    int tid = threadIdx.x;
    int w = tid >> 5, lane = tid & 31;
    int g = lane >> 2, t4 = lane & 3;
    int wr = w >> 2, wc = w & 3;          // warp grid 2 x 4
    int b = blockIdx.x;

    // triangular decode (bi <= bj)
    int bi = (int)((2.f * TILES + 1.f -
                    sqrtf((float)((2 * TILES + 1) * (2 * TILES + 1) - 8 * b))) * 0.5f);
    if (bi < 0) bi = 0; if (bi > TILES - 1) bi = TILES - 1;
    while (bi > 0 && bi * TILES - bi * (bi - 1) / 2 > b) bi--;
    while ((bi + 1) * TILES - (bi + 1) * bi / 2 <= b) bi++;
    int bj = bi + (b - (bi * TILES - bi * (bi - 1) / 2));

    int p0 = bi * 128, q0 = bj * 128;
    const float* xA = g_xr + (size_t)p0 * Dd;
    const float* xB = g_xr + (size_t)q0 * Dd;

    // ---- stage u vectors (scaled, sign-carrying) + squared norms ----
    if (tid < 128) {
        int p = p0 + tid;
        sqP[tid] = g_sq[p];
        if (p < Bsz) {
            #pragma unroll
            for (int c = 0; c < Ccls; c++)
                uPs[c * USTR + tid] = slab[(size_t)p * Ccls + c] * g_sscale[c];
        } else {
            #pragma unroll
            for (int c = 0; c < Ccls; c++)
                uPs[c * USTR + tid] = tlog[(size_t)(p - Bsz) * Ccls + c] * g_tscale[c];
        }
    } else {
        int j = tid - 128;
        int q = q0 + j;
        sqQ[j] = g_sq[q];
        if (q < Bsz) {
            #pragma unroll
            for (int c = 0; c < Ccls; c++)
                uQs[c * USTR + j] = slab[(size_t)q * Ccls + c] * g_sscale[c];
        } else {
            #pragma unroll
            for (int c = 0; c < Ccls; c++)
                uQs[c * USTR + j] = tlog[(size_t)(q - Bsz) * Ccls + c] * g_tscale[c];
        }
    }

    // per-thread cp.async coordinates: 4 (row, chunk) pairs per operand
    int prow[4], pch[4];
    uint32_t pdst[4];
    #pragma unroll
    for (int i = 0; i < 4; i++) {
        int gg = tid + 256 * i;               // 0..1023
        prow[i] = gg >> 3;
        pch[i]  = gg & 7;
        pdst[i] = (uint32_t)(prow[i] * 128 + ((pch[i] ^ (prow[i] & 7)) * 16));
    }

    // prefetch chunk 0 into buf 0
    {
        uint32_t sA = smb + OFF_BUF;
        uint32_t sB = sA + 16384u;
        #pragma unroll
        for (int i = 0; i < 4; i++) {
            CP_ASYNC16(sA + pdst[i], xA + (size_t)prow[i] * Dd + pch[i] * 4);
            CP_ASYNC16(sB + pdst[i], xB + (size_t)prow[i] * Dd + pch[i] * 4);
        }
        CP_COMMIT();
    }

    // per-lane ldmatrix base geometry
    int rx = lane & 7;                            // row & 7 for both A and B
    uint32_t baseA = (uint32_t)((wr * 64 + (lane & 7) + ((lane >> 3) & 1) * 8) * 128);
    uint32_t hiA = (uint32_t)(lane >> 4);         // 0: chunk 2ks, 1: 2ks+1
    uint32_t baseB = (uint32_t)(16384 + (wc * 32 + (lane & 7)) * 128);
    uint32_t hiB = (uint32_t)((lane >> 3) & 1);

    float acc[16][4];
    #pragma unroll
    for (int i = 0; i < 16; i++)
        #pragma unroll
        for (int j = 0; j < 4; j++) acc[i][j] = 0.f;

    // ---- mainloop: 8 K-chunks of 32, double buffered ----
    for (int ch = 0; ch < 8; ch++) {
        int buf = ch & 1;
        if (ch < 7) {
            uint32_t sA = smb + OFF_BUF + (buf ^ 1) * 32768u;
            uint32_t sB = sA + 16384u;
            int ko = (ch + 1) * 32;
            #pragma unroll
            for (int i = 0; i < 4; i++) {
                CP_ASYNC16(sA + pdst[i], xA + (size_t)prow[i] * Dd + ko + pch[i] * 4);
                CP_ASYNC16(sB + pdst[i], xB + (size_t)prow[i] * Dd + ko + pch[i] * 4);
            }
            CP_COMMIT();
            CP_WAIT(1);
        } else {
            CP_WAIT(0);
        }
        __syncthreads();

        uint32_t bufb = smb + OFF_BUF + buf * 32768u;
        uint32_t fA[2][4][4];
        uint32_t fB[2][4][2];

        // load ks=0 fragments
        {
            uint32_t ka = ((hiA ^ (uint32_t)rx) << 4);
            uint32_t kb = ((hiB ^ (uint32_t)rx) << 4);
            #pragma unroll
            for (int mi = 0; mi < 4; mi++)
                ldsm_x4(fA[0][mi], bufb + baseA + mi * 2048u + ka);
            #pragma unroll
            for (int ni = 0; ni < 4; ni++)
                ldsm_x2(fB[0][ni], bufb + baseB + ni * 1024u + kb);
        }
        #pragma unroll
        for (int ks = 0; ks < 4; ks++) {
            int cur = ks & 1;
            if (ks < 3) {
                uint32_t kn = (uint32_t)((ks + 1) << 1);
                uint32_t ka = (((kn | hiA) ^ (uint32_t)rx) << 4);
                uint32_t kb = (((kn | hiB) ^ (uint32_t)rx) << 4);
                #pragma unroll
                for (int mi = 0; mi < 4; mi++)
                    ldsm_x4(fA[cur ^ 1][mi], bufb + baseA + mi * 2048u + ka);
                #pragma unroll
                for (int ni = 0; ni < 4; ni++)
                    ldsm_x2(fB[cur ^ 1][ni], bufb + baseB + ni * 1024u + kb);
            }
            #pragma unroll
            for (int mi = 0; mi < 4; mi++)
                #pragma unroll
                for (int ni = 0; ni < 4; ni++)
                    mma_tf32(acc[mi * 4 + ni], fA[cur][mi], fB[cur][ni]);
        }
        __syncthreads();
    }

    // ---- epilogue ----
    const float Ce = g_expC;
    const float scale = g_invcount * ((bi == bj) ? 1.f : 2.f);
    float partial = 0.f;

    #pragma unroll
    for (int mi = 0; mi < 4; mi++) {
        int r0 = wr * 64 + mi * 16 + g;
        int r1 = r0 + 8;
        float up0[Ccls], up1[Ccls];
        #pragma unroll
        for (int c = 0; c < Ccls; c++) {
            up0[c] = uPs[c * USTR + r0];
            up1[c] = uPs[c * USTR + r1];
        }
        float sp0 = sqP[r0], sp1 = sqP[r1];
        #pragma unroll
        for (int ni = 0; ni < 4; ni++) {
            float* a = acc[mi * 4 + ni];
            int cbx = wc * 32 + ni * 8 + 2 * t4;
            float2 sv = *(float2*)&sqQ[cbx];
            float w00 = 0.f, w01 = 0.f, w10 = 0.f, w11 = 0.f;
            #pragma unroll
            for (int c = 0; c < Ccls; c++) {
                float2 uq = *(float2*)&uQs[c * USTR + cbx];
                w00 = fmaf(up0[c], uq.x, w00);
                w01 = fmaf(up0[c], uq.y, w01);
                w10 = fmaf(up1[c], uq.x, w10);
                w11 = fmaf(up1[c], uq.y, w11);
            }
            float l2, z, z2, z4, z8;
            l2 = fmaxf(sp0 + sv.x - 2.f * a[0], 0.f);
            z = __expf(-l2 * Ce); z2 = z * z; z4 = z2 * z2; z8 = z4 * z4;
            partial = fmaf(w00, z + z2 + z4 + z8 + z8 * z8, partial);
            l2 = fmaxf(sp0 + sv.y - 2.f * a[1], 0.f);
            z = __expf(-l2 * Ce); z2 = z * z; z4 = z2 * z2; z8 = z4 * z4;
            partial = fmaf(w01, z + z2 + z4 + z8 + z8 * z8, partial);
            l2 = fmaxf(sp1 + sv.x - 2.f * a[2], 0.f);
            z = __expf(-l2 * Ce); z2 = z * z; z4 = z2 * z2; z8 = z4 * z4;
            partial = fmaf(w10, z + z2 + z4 + z8 + z8 * z8, partial);
            l2 = fmaxf(sp1 + sv.y - 2.f * a[3], 0.f);
            z = __expf(-l2 * Ce); z2 = z * z; z4 = z2 * z2; z8 = z4 * z4;
            partial = fmaf(w11, z + z2 + z4 + z8 + z8 * z8, partial);
        }
    }
    partial *= scale;

    #pragma unroll
    for (int o = 16; o; o >>= 1) partial += __shfl_xor_sync(0xffffffffu, partial, o);
    if (lane == 0) red[w] = partial;
    __syncthreads();
    if (tid == 0) {
        float s = 0.f;
        #pragma unroll
        for (int i = 0; i < 8; i++) s += red[i];
        atomicAdd(out, s);
    }
}

// ---------------- launcher ------------------------------------------------
extern "C" void kernel_launch(void* const* d_in, const int* in_sizes, int n_in,
                              void* d_out, int out_size) {
    const float* src  = (const float*)d_in[0];
    const float* tgt  = (const float*)d_in[1];
    const float* slab = (const float*)d_in[2];
    const float* tlog = (const float*)d_in[3];
    float* out = (float*)d_out;

    static int configured = 0;
    if (!configured) {
        cudaFuncSetAttribute(k_main, cudaFuncAttributeMaxDynamicSharedMemorySize, SMEM_DYN);
        configured = 1;
    }

    k_row<<<Nrows / 32, 256>>>(src, tgt, slab, tlog, out);
    k_main<<<NBLK, 256, SMEM_DYN>>>(slab, tlog, out);
}

// round 6
// speedup vs baseline: 3.1744x; 1.0858x over previous
#include <cuda_runtime.h>
#include <cstdint>
#include <math.h>

#define Bsz   4096
#define Dd    256
#define Ccls  10
#define Nrows 8192
#define TILES 64          // 8192 / 128
#define NBLK  2080        // 64*65/2 triangular tiles
#define USTR  132         // class-major u stride (floats)

// ===================== device scratch ====================================
// tf32-rounded copy, chunk-major and pre-swizzled:
// g_xr[ch][row][ ((c16 ^ (row&7))<<2) | c4 ]  for source column ch*32 + c16*4 + c4
__device__ __align__(16) float g_xr[8][Nrows][32];
__device__ float g_sq[Nrows];
__device__ float g_spart[128][Ccls];
__device__ float g_tpart[128][Ccls];
__device__ int   g_cpart[128][Ccls];
__device__ float g_vpart[256][256];   // per-block column sums
__device__ float g_qpart[256];        // per-block sum of squared norms
__device__ float g_sscale[Ccls];
__device__ float g_tscale[Ccls];      // carries minus sign for target rows
__device__ float g_expC;              // 1/(4*bw_raw)
__device__ float g_invcount;
__device__ unsigned g_ctr;            // last-block counter (monotonic)

// ---------------- helpers -------------------------------------------------
__device__ __forceinline__ uint32_t f2tf32(float v) {
    uint32_t u;
    asm("cvt.rna.tf32.f32 %0, %1;" : "=r"(u) : "f"(v));
    return u;
}
__device__ __forceinline__ void mma_tf32(float* d, const uint32_t* a, const uint32_t* b) {
    asm volatile(
        "mma.sync.aligned.m16n8k8.row.col.f32.tf32.tf32.f32 "
        "{%0,%1,%2,%3}, {%4,%5,%6,%7}, {%8,%9}, {%0,%1,%2,%3};"
        : "+f"(d[0]), "+f"(d[1]), "+f"(d[2]), "+f"(d[3])
        : "r"(a[0]), "r"(a[1]), "r"(a[2]), "r"(a[3]), "r"(b[0]), "r"(b[1]));
}
__device__ __forceinline__ void ldsm_x4(uint32_t* r, uint32_t addr) {
    asm volatile("ldmatrix.sync.aligned.m8n8.x4.shared.b16 {%0,%1,%2,%3}, [%4];"
        : "=r"(r[0]), "=r"(r[1]), "=r"(r[2]), "=r"(r[3]) : "r"(addr));
}
__device__ __forceinline__ void ldsm_x2(uint32_t* r, uint32_t addr) {
    asm volatile("ldmatrix.sync.aligned.m8n8.x2.shared.b16 {%0,%1}, [%2];"
        : "=r"(r[0]), "=r"(r[1]) : "r"(addr));
}
__device__ __forceinline__ uint32_t smem_u32(const void* p) {
    return (uint32_t)__cvta_generic_to_shared(p);
}
#define MBAR_INIT(mbar, cnt) \
    asm volatile("mbarrier.init.shared.b64 [%0], %1;" \
                 :: "r"((uint32_t)(mbar)), "r"((uint32_t)(cnt)) : "memory")
#define MBAR_EXPECT_TX(mbar, bytes) \
    asm volatile("mbarrier.arrive.expect_tx.shared.b64 _, [%0], %1;" \
                 :: "r"((uint32_t)(mbar)), "r"((uint32_t)(bytes)) : "memory")
#define BULK_G2S(dst, src, bytes, mbar) \
    asm volatile("cp.async.bulk.shared::cluster.global.mbarrier::complete_tx::bytes " \
                 "[%0], [%1], %2, [%3];" \
                 :: "r"((uint32_t)(dst)), "l"(src), "r"((uint32_t)(bytes)), \
                    "r"((uint32_t)(mbar)) : "memory")
#define MBAR_WAIT(mbar, parity) do {                                             \
    uint32_t _m = (uint32_t)(mbar); uint32_t _p = (uint32_t)(parity);            \
    uint32_t _done;                                                              \
    asm volatile("{\n\t.reg .pred p;\n\t"                                        \
        "mbarrier.try_wait.parity.acquire.cta.shared::cta.b64 p, [%1], %2;\n\t"  \
        "selp.b32 %0, 1, 0, p;\n\t}" : "=r"(_done) : "r"(_m), "r"(_p) : "memory"); \
    if (!_done) {                                                                \
        asm volatile("{\n\t.reg .pred P1;\n\t"                                   \
            "W_%=:\n\t"                                                          \
            "mbarrier.try_wait.parity.acquire.cta.shared::cta.b64 P1, [%0], %1, 0x989680;\n\t" \
            "@P1 bra.uni D_%=;\n\tbra.uni W_%=;\n\tD_%=:\n\t}"                   \
            :: "r"(_m), "r"(_p) : "memory");                                     \
    }                                                                            \
} while (0)

// ---------------- kernel 1: rows + stats + (last block) finalize ----------
__global__ void k_row(const float* __restrict__ src,
                      const float* __restrict__ tgt,
                      const float* __restrict__ slab,
                      const float* __restrict__ tlog,
                      float* __restrict__ out) {
    __shared__ float scol[8][256];
    __shared__ float bs[8];
    __shared__ float sp10[Ccls];
    __shared__ int   cp10[Ccls];
    __shared__ int   lastFlag;
    int tid = threadIdx.x;
    int w = tid >> 5, lane = tid & 31;
    int bid = blockIdx.x;

    // ---- warp 0: label/logit column stats for this block's 32 rows ----
    if (w == 0) {
        if (lane < Ccls) { sp10[lane] = 0.f; cp10[lane] = 0; }
        __syncwarp();
        int r = bid * 32 + lane;
        if (bid < 128) {
            #pragma unroll
            for (int c = 0; c < Ccls; c++)
                atomicAdd(&sp10[c], slab[(size_t)r * Ccls + c]);
        } else {
            int rr = r - Bsz;
            float best = -1.f; int bx = 0;
            #pragma unroll
            for (int c = 0; c < Ccls; c++) {
                float tv = tlog[(size_t)rr * Ccls + c];
                atomicAdd(&sp10[c], tv);
                if (tv > best) { best = tv; bx = c; }
            }
            atomicAdd(&cp10[bx], 1);
        }
        __syncwarp();
        if (lane < Ccls) {
            if (bid < 128) g_spart[bid][lane] = sp10[lane];
            else { g_tpart[bid - 128][lane] = sp10[lane];
                   g_cpart[bid - 128][lane] = cp10[lane]; }
        }
    }

    // ---- row norms + column sums + tf32 pre-round (pre-swizzled store) ----
    #pragma unroll
    for (int i = 0; i < 8; i++) scol[w][lane + 32 * i] = 0.f;
    float wsq = 0.f;
    #pragma unroll
    for (int k = 0; k < 4; k++) {
        int row = bid * 32 + w * 4 + k;
        const float* p = (row < Bsz) ? src + (size_t)row * Dd
                                     : tgt + (size_t)(row - Bsz) * Dd;
        int sw = ((lane >> 2) ^ (row & 7)) * 4 + (lane & 3);
        float s = 0.f;
        #pragma unroll
        for (int i = 0; i < 8; i++) {
            float v = p[lane + 32 * i];
            s += v * v;
            scol[w][lane + 32 * i] += v;
            g_xr[i][row][sw] = __uint_as_float(f2tf32(v));
        }
        #pragma unroll
        for (int o = 16; o; o >>= 1) s += __shfl_xor_sync(0xffffffffu, s, o);
        if (lane == 0) { g_sq[row] = s; wsq += s; }
    }
    if (lane == 0) bs[w] = wsq;
    __syncthreads();
    float cs = 0.f;
    #pragma unroll
    for (int ww = 0; ww < 8; ww++) cs += scol[ww][tid];
    g_vpart[bid][tid] = cs;
    if (tid == 0) {
        float tot = 0.f;
        #pragma unroll
        for (int i = 0; i < 8; i++) tot += bs[i];
        g_qpart[bid] = tot;
    }

    // ---- last block finalizes ----
    __threadfence();
    if (tid == 0) {
        unsigned old = atomicAdd(&g_ctr, 1u);
        lastFlag = (((old + 1u) & 255u) == 0u);
    }
    __syncthreads();
    if (!lastFlag) return;

    __shared__ float red[256];
    __shared__ float ssumS[Ccls];
    __shared__ int   cntS[Ccls];
    int t = tid;
    if (t < Ccls) {
        float ss = 0.f, ts = 0.f; int cc = 0;
        #pragma unroll 4
        for (int b2 = 0; b2 < 128; b2++) {
            ss += g_spart[b2][t];
            ts += g_tpart[b2][t];
            cc += g_cpart[b2][t];
        }
        ssumS[t] = ss; cntS[t] = cc;
        bool mask = (ss > 0.f) && (cc > 0);
        g_sscale[t] = mask ? (1.f / ss) : 0.f;
        float te = (ts == 0.f) ? 100.f : ts;
        g_tscale[t] = mask ? (-1.f / te) : 0.f;
    }
    float v = 0.f;
    #pragma unroll 8
    for (int b2 = 0; b2 < 256; b2++) v += g_vpart[b2][t];
    red[t] = v * v;
    __syncthreads();
    for (int s = 128; s; s >>= 1) { if (t < s) red[t] += red[t + s]; __syncthreads(); }
    float VV = red[0];
    __syncthreads();
    red[t] = g_qpart[t];
    __syncthreads();
    for (int s = 128; s; s >>= 1) { if (t < s) red[t] += red[t + s]; __syncthreads(); }
    if (t == 0) {
        int count = 0;
        for (int c = 0; c < Ccls; c++)
            if (ssumS[c] > 0.f && cntS[c] > 0) count++;
        float S = red[0];
        float sum_l2 = 2.f * (float)Nrows * S - 2.f * VV;
        float nf = (float)Nrows;
        float bw_raw = sum_l2 / (nf * nf - nf);
        g_expC = 1.f / (4.f * bw_raw);
        g_invcount = (count > 0) ? 1.f / (float)count : 0.f;
        out[0] = 0.f;
    }
}

// ---------------- kernel 2: tf32 mma pairwise GEMM + MMD epilogue ---------
// 128x128 tile (triangular grid), 256 threads = 8 warps (2x4), warp tile
// 64x32, m16n8k8 tf32. Operands arrive pre-swizzled via cp.async.bulk into a
// 3-stage smem pipeline; ldmatrix fragment loads, ks-level software pipeline.
#define NSTAGE  3
#define STAGEB  32768                   // A 16KB + B 16KB
#define OFF_BUF 0
#define OFF_MBAR (NSTAGE * STAGEB)      // 3 x 8B
#define OFF_UP  (OFF_MBAR + 64)
#define OFF_UQ  (OFF_UP + Ccls * USTR * 4)
#define OFF_SQP (OFF_UQ + Ccls * USTR * 4)
#define OFF_SQQ (OFF_SQP + 512)
#define OFF_RED (OFF_SQQ + 512)
#define SMEM_DYN (OFF_RED + 64)

__global__ void __launch_bounds__(256, 2) k_main(
    const float* __restrict__ slab, const float* __restrict__ tlog,
    float* __restrict__ out)
{
    extern __shared__ char sm[];
    float* uPs = (float*)(sm + OFF_UP);   // [10][USTR]
    float* uQs = (float*)(sm + OFF_UQ);
    float* sqP = (float*)(sm + OFF_SQP);
    float* sqQ = (float*)(sm + OFF_SQQ);
    float* red = (float*)(sm + OFF_RED);
    uint32_t smb = smem_u32(sm);

    int tid = threadIdx.x;
    int w = tid >> 5, lane = tid & 31;
    int g = lane >> 2, t4 = lane & 3;
    int wr = w >> 2, wc = w & 3;          // warp grid 2 x 4
    int b = blockIdx.x;

    // triangular decode (bi <= bj)
    int bi = (int)((2.f * TILES + 1.f -
                    sqrtf((float)((2 * TILES + 1) * (2 * TILES + 1) - 8 * b))) * 0.5f);
    if (bi < 0) bi = 0; if (bi > TILES - 1) bi = TILES - 1;
    while (bi > 0 && bi * TILES - bi * (bi - 1) / 2 > b) bi--;
    while ((bi + 1) * TILES - (bi + 1) * bi / 2 <= b) bi++;
    int bj = bi + (b - (bi * TILES - bi * (bi - 1) / 2));

    int p0 = bi * 128, q0 = bj * 128;

    // ---- mbarrier init + prefetch first NSTAGE chunks ----
    if (tid == 0) {
        #pragma unroll
        for (int s = 0; s < NSTAGE; s++) MBAR_INIT(smb + OFF_MBAR + 8 * s, 1);
    }
    __syncthreads();
    if (tid == 0) {
        #pragma unroll
        for (int s = 0; s < NSTAGE; s++) {
            uint32_t mb = smb + OFF_MBAR + 8 * s;
            uint32_t dst = smb + OFF_BUF + s * STAGEB;
            MBAR_EXPECT_TX(mb, 2 * 16384);
            BULK_G2S(dst,          &g_xr[s][p0][0], 16384, mb);
            BULK_G2S(dst + 16384u, &g_xr[s][q0][0], 16384, mb);
        }
    }

    // ---- stage u vectors (scaled, sign-carrying) + squared norms ----
    if (tid < 128) {
        int p = p0 + tid;
        sqP[tid] = g_sq[p];
        if (p < Bsz) {
            #pragma unroll
            for (int c = 0; c < Ccls; c++)
                uPs[c * USTR + tid] = slab[(size_t)p * Ccls + c] * g_sscale[c];
        } else {
            #pragma unroll
            for (int c = 0; c < Ccls; c++)
                uPs[c * USTR + tid] = tlog[(size_t)(p - Bsz) * Ccls + c] * g_tscale[c];
        }
    } else {
        int j = tid - 128;
        int q = q0 + j;
        sqQ[j] = g_sq[q];
        if (q < Bsz) {
            #pragma unroll
            for (int c = 0; c < Ccls; c++)
                uQs[c * USTR + j] = slab[(size_t)q * Ccls + c] * g_sscale[c];
        } else {
            #pragma unroll
            for (int c = 0; c < Ccls; c++)
                uQs[c * USTR + j] = tlog[(size_t)(q - Bsz) * Ccls + c] * g_tscale[c];
        }
    }

    // per-lane ldmatrix base geometry (offsets within a stage buffer)
    int rx = lane & 7;
    uint32_t baseA = (uint32_t)((wr * 64 + (lane & 7) + ((lane >> 3) & 1) * 8) * 128);
    uint32_t hiA = (uint32_t)(lane >> 4);
    uint32_t baseB = (uint32_t)(16384 + (wc * 32 + (lane & 7)) * 128);
    uint32_t hiB = (uint32_t)((lane >> 3) & 1);

    float acc[16][4];
    #pragma unroll
    for (int i = 0; i < 16; i++)
        #pragma unroll
        for (int j = 0; j < 4; j++) acc[i][j] = 0.f;

    // ---- mainloop: 8 K-chunks of 32, 3-stage bulk-async pipeline ----
    #pragma unroll 1
    for (int ch = 0; ch < 8; ch++) {
        int st = ch % NSTAGE;
        int ph = (ch / NSTAGE) & 1;
        MBAR_WAIT(smb + OFF_MBAR + 8 * st, ph);

        uint32_t bufb = smb + OFF_BUF + st * STAGEB;
        uint32_t fA[2][4][4];
        uint32_t fB[2][4][2];

        {
            uint32_t ka = ((hiA ^ (uint32_t)rx) << 4);
            uint32_t kb = ((hiB ^ (uint32_t)rx) << 4);
            #pragma unroll
            for (int mi = 0; mi < 4; mi++)
                ldsm_x4(fA[0][mi], bufb + baseA + mi * 2048u + ka);
            #pragma unroll
            for (int ni = 0; ni < 4; ni++)
                ldsm_x2(fB[0][ni], bufb + baseB + ni * 1024u + kb);
        }
        #pragma unroll
        for (int ks = 0; ks < 4; ks++) {
            int cur = ks & 1;
            if (ks < 3) {
                uint32_t kn = (uint32_t)((ks + 1) << 1);
                uint32_t ka = (((kn | hiA) ^ (uint32_t)rx) << 4);
                uint32_t kb = (((kn | hiB) ^ (uint32_t)rx) << 4);
                #pragma unroll
                for (int mi = 0; mi < 4; mi++)
                    ldsm_x4(fA[cur ^ 1][mi], bufb + baseA + mi * 2048u + ka);
                #pragma unroll
                for (int ni = 0; ni < 4; ni++)
                    ldsm_x2(fB[cur ^ 1][ni], bufb + baseB + ni * 1024u + kb);
            }
            #pragma unroll
            for (int mi = 0; mi < 4; mi++)
                #pragma unroll
                for (int ni = 0; ni < 4; ni++)
                    mma_tf32(acc[mi * 4 + ni], fA[cur][mi], fB[cur][ni]);
        }
        __syncthreads();          // all warps done reading stage st
        if (tid == 0 && ch + NSTAGE < 8) {
            int nc = ch + NSTAGE;
            uint32_t mb = smb + OFF_MBAR + 8 * st;
            uint32_t dst = smb + OFF_BUF + st * STAGEB;
            MBAR_EXPECT_TX(mb, 2 * 16384);
            BULK_G2S(dst,          &g_xr[nc][p0][0], 16384, mb);
            BULK_G2S(dst + 16384u, &g_xr[nc][q0][0], 16384, mb);
        }
    }

    // ---- epilogue ----
    const float Ce = g_expC;
    const float scale = g_invcount * ((bi == bj) ? 1.f : 2.f);
    float partial = 0.f;

    #pragma unroll
    for (int mi = 0; mi < 4; mi++) {
        int r0 = wr * 64 + mi * 16 + g;
        int r1 = r0 + 8;
        float up0[Ccls], up1[Ccls];
        #pragma unroll
        for (int c = 0; c < Ccls; c++) {
            up0[c] = uPs[c * USTR + r0];
            up1[c] = uPs[c * USTR + r1];
        }
        float sp0 = sqP[r0], sp1 = sqP[r1];
        #pragma unroll
        for (int ni = 0; ni < 4; ni++) {
            float* a = acc[mi * 4 + ni];
            int cbx = wc * 32 + ni * 8 + 2 * t4;
            float2 sv = *(float2*)&sqQ[cbx];
            float w00 = 0.f, w01 = 0.f, w10 = 0.f, w11 = 0.f;
            #pragma unroll
            for (int c = 0; c < Ccls; c++) {
                float2 uq = *(float2*)&uQs[c * USTR + cbx];
                w00 = fmaf(up0[c], uq.x, w00);
                w01 = fmaf(up0[c], uq.y, w01);
                w10 = fmaf(up1[c], uq.x, w10);
                w11 = fmaf(up1[c], uq.y, w11);
            }
            float l2, z, z2, z4, z8;
            l2 = fmaxf(sp0 + sv.x - 2.f * a[0], 0.f);
            z = __expf(-l2 * Ce); z2 = z * z; z4 = z2 * z2; z8 = z4 * z4;
            partial = fmaf(w00, z + z2 + z4 + z8 + z8 * z8, partial);
            l2 = fmaxf(sp0 + sv.y - 2.f * a[1], 0.f);
            z = __expf(-l2 * Ce); z2 = z * z; z4 = z2 * z2; z8 = z4 * z4;
            partial = fmaf(w01, z + z2 + z4 + z8 + z8 * z8, partial);
            l2 = fmaxf(sp1 + sv.x - 2.f * a[2], 0.f);
            z = __expf(-l2 * Ce); z2 = z * z; z4 = z2 * z2; z8 = z4 * z4;
            partial = fmaf(w10, z + z2 + z4 + z8 + z8 * z8, partial);
            l2 = fmaxf(sp1 + sv.y - 2.f * a[3], 0.f);
            z = __expf(-l2 * Ce); z2 = z * z; z4 = z2 * z2; z8 = z4 * z4;
            partial = fmaf(w11, z + z2 + z4 + z8 + z8 * z8, partial);
        }
    }
    partial *= scale;

    #pragma unroll
    for (int o = 16; o; o >>= 1) partial += __shfl_xor_sync(0xffffffffu, partial, o);
    if (lane == 0) red[w] = partial;
    __syncthreads();
    if (tid == 0) {
        float s = 0.f;
        #pragma unroll
        for (int i = 0; i < 8; i++) s += red[i];
        atomicAdd(out, s);
    }
}

// ---------------- launcher ------------------------------------------------
extern "C" void kernel_launch(void* const* d_in, const int* in_sizes, int n_in,
                              void* d_out, int out_size) {
    const float* src  = (const float*)d_in[0];
    const float* tgt  = (const float*)d_in[1];
    const float* slab = (const float*)d_in[2];
    const float* tlog = (const float*)d_in[3];
    float* out = (float*)d_out;

    static int configured = 0;
    if (!configured) {
        cudaFuncSetAttribute(k_main, cudaFuncAttributeMaxDynamicSharedMemorySize, SMEM_DYN);
        configured = 1;
    }

    k_row<<<Nrows / 32, 256>>>(src, tgt, slab, tlog, out);
    k_main<<<NBLK, 256, SMEM_DYN>>>(slab, tlog, out);
}

// round 7
// speedup vs baseline: 4.0889x; 1.2881x over previous
#include <cuda_runtime.h>
#include <cuda_fp16.h>
#include <cstdint>
#include <math.h>

#define Bsz   4096
#define Dd    256
#define Ccls  10
#define Nrows 8192
#define TILES 64          // 8192 / 128
#define NBLK  2080        // 64*65/2 triangular tiles
#define USTR  132         // class-major u stride (floats)

// ===================== device scratch ====================================
// fp16 copy, chunk-major (64 cols per chunk) and pre-swizzled:
// within a 128B row, 16B unit u of column c stored at u ^ (row&7).
__device__ __align__(16) __half g_xh[4][Nrows][64];
__device__ float g_sq[Nrows];
__device__ float g_spart[128][Ccls];
__device__ float g_tpart[128][Ccls];
__device__ int   g_cpart[128][Ccls];
__device__ float g_vpart[256][256];   // per-block column sums
__device__ float g_qpart[256];        // per-block sum of squared norms
__device__ float g_sscale[Ccls];
__device__ float g_tscale[Ccls];      // carries minus sign for target rows
__device__ float g_expC;              // 1/(4*bw_raw)
__device__ float g_invcount;
__device__ unsigned g_ctr;            // last-block counter (monotonic)

// ---------------- helpers -------------------------------------------------
__device__ __forceinline__ void mma_f16(float* d, const uint32_t* a, const uint32_t* b) {
    asm volatile(
        "mma.sync.aligned.m16n8k16.row.col.f32.f16.f16.f32 "
        "{%0,%1,%2,%3}, {%4,%5,%6,%7}, {%8,%9}, {%0,%1,%2,%3};"
        : "+f"(d[0]), "+f"(d[1]), "+f"(d[2]), "+f"(d[3])
        : "r"(a[0]), "r"(a[1]), "r"(a[2]), "r"(a[3]), "r"(b[0]), "r"(b[1]));
}
__device__ __forceinline__ void ldsm_x4(uint32_t* r, uint32_t addr) {
    asm volatile("ldmatrix.sync.aligned.m8n8.x4.shared.b16 {%0,%1,%2,%3}, [%4];"
        : "=r"(r[0]), "=r"(r[1]), "=r"(r[2]), "=r"(r[3]) : "r"(addr));
}
__device__ __forceinline__ uint32_t smem_u32(const void* p) {
    return (uint32_t)__cvta_generic_to_shared(p);
}
#define MBAR_INIT(mbar, cnt) \
    asm volatile("mbarrier.init.shared.b64 [%0], %1;" \
                 :: "r"((uint32_t)(mbar)), "r"((uint32_t)(cnt)) : "memory")
#define MBAR_EXPECT_TX(mbar, bytes) \
    asm volatile("mbarrier.arrive.expect_tx.shared.b64 _, [%0], %1;" \
                 :: "r"((uint32_t)(mbar)), "r"((uint32_t)(bytes)) : "memory")
#define BULK_G2S(dst, src, bytes, mbar) \
    asm volatile("cp.async.bulk.shared::cluster.global.mbarrier::complete_tx::bytes " \
                 "[%0], [%1], %2, [%3];" \
                 :: "r"((uint32_t)(dst)), "l"(src), "r"((uint32_t)(bytes)), \
                    "r"((uint32_t)(mbar)) : "memory")
#define MBAR_WAIT(mbar, parity) do {                                             \
    uint32_t _m = (uint32_t)(mbar); uint32_t _p = (uint32_t)(parity);            \
    uint32_t _done;                                                              \
    asm volatile("{\n\t.reg .pred p;\n\t"                                        \
        "mbarrier.try_wait.parity.acquire.cta.shared::cta.b64 p, [%1], %2;\n\t"  \
        "selp.b32 %0, 1, 0, p;\n\t}" : "=r"(_done) : "r"(_m), "r"(_p) : "memory"); \
    if (!_done) {                                                                \
        asm volatile("{\n\t.reg .pred P1;\n\t"                                   \
            "W_%=:\n\t"                                                          \
            "mbarrier.try_wait.parity.acquire.cta.shared::cta.b64 P1, [%0], %1, 0x989680;\n\t" \
            "@P1 bra.uni D_%=;\n\tbra.uni W_%=;\n\tD_%=:\n\t}"                   \
            :: "r"(_m), "r"(_p) : "memory");                                     \
    }                                                                            \
} while (0)

// ---------------- kernel 1: rows + stats + (last block) finalize ----------
__global__ void k_row(const float* __restrict__ src,
                      const float* __restrict__ tgt,
                      const float* __restrict__ slab,
                      const float* __restrict__ tlog,
                      float* __restrict__ out) {
    __shared__ float scol[8][256];
    __shared__ float bs[8];
    __shared__ float sp10[Ccls];
    __shared__ int   cp10[Ccls];
    __shared__ int   lastFlag;
    int tid = threadIdx.x;
    int w = tid >> 5, lane = tid & 31;
    int bid = blockIdx.x;

    // ---- warp 0: label/logit column stats for this block's 32 rows ----
    if (w == 0) {
        if (lane < Ccls) { sp10[lane] = 0.f; cp10[lane] = 0; }
        __syncwarp();
        int r = bid * 32 + lane;
        if (bid < 128) {
            #pragma unroll
            for (int c = 0; c < Ccls; c++)
                atomicAdd(&sp10[c], slab[(size_t)r * Ccls + c]);
        } else {
            int rr = r - Bsz;
            float best = -1.f; int bx = 0;
            #pragma unroll
            for (int c = 0; c < Ccls; c++) {
                float tv = tlog[(size_t)rr * Ccls + c];
                atomicAdd(&sp10[c], tv);
                if (tv > best) { best = tv; bx = c; }
            }
            atomicAdd(&cp10[bx], 1);
        }
        __syncwarp();
        if (lane < Ccls) {
            if (bid < 128) g_spart[bid][lane] = sp10[lane];
            else { g_tpart[bid - 128][lane] = sp10[lane];
                   g_cpart[bid - 128][lane] = cp10[lane]; }
        }
    }

    // ---- row norms + column sums + fp16 pre-round (pre-swizzled) ----
    #pragma unroll
    for (int i = 0; i < 8; i++) scol[w][lane + 32 * i] = 0.f;
    __syncwarp();
    float wsq = 0.f;
    int c0 = 2 * lane;                       // 0..62, even
    int uu = c0 >> 3, oo = c0 & 7;
    #pragma unroll
    for (int k = 0; k < 4; k++) {
        int row = bid * 32 + w * 4 + k;
        const float* p = (row < Bsz) ? src + (size_t)row * Dd
                                     : tgt + (size_t)(row - Bsz) * Dd;
        int rx = row & 7;
        int sw = (((uu ^ rx) << 3) | oo);    // half index within 64-half row
        float s = 0.f;
        #pragma unroll
        for (int i = 0; i < 4; i++) {
            float2 v = *(const float2*)(p + c0 + 64 * i);
            s += v.x * v.x + v.y * v.y;
            float2 acc = *(float2*)&scol[w][c0 + 64 * i];
            acc.x += v.x; acc.y += v.y;
            *(float2*)&scol[w][c0 + 64 * i] = acc;
            *(__half2*)&g_xh[i][row][sw] = __floats2half2_rn(v.x, v.y);
        }
        #pragma unroll
        for (int o = 16; o; o >>= 1) s += __shfl_xor_sync(0xffffffffu, s, o);
        if (lane == 0) { g_sq[row] = s; wsq += s; }
    }
    if (lane == 0) bs[w] = wsq;
    __syncthreads();
    float cs = 0.f;
    #pragma unroll
    for (int ww = 0; ww < 8; ww++) cs += scol[ww][tid];
    g_vpart[bid][tid] = cs;
    if (tid == 0) {
        float tot = 0.f;
        #pragma unroll
        for (int i = 0; i < 8; i++) tot += bs[i];
        g_qpart[bid] = tot;
    }

    // ---- last block finalizes ----
    __threadfence();
    if (tid == 0) {
        unsigned old = atomicAdd(&g_ctr, 1u);
        lastFlag = (((old + 1u) & 255u) == 0u);
    }
    __syncthreads();
    if (!lastFlag) return;

    __shared__ float red[256];
    __shared__ float ssumS[Ccls];
    __shared__ int   cntS[Ccls];
    int t = tid;
    if (t < Ccls) {
        float ss = 0.f, ts = 0.f; int cc = 0;
        #pragma unroll 4
        for (int b2 = 0; b2 < 128; b2++) {
            ss += g_spart[b2][t];
            ts += g_tpart[b2][t];
            cc += g_cpart[b2][t];
        }
        ssumS[t] = ss; cntS[t] = cc;
        bool mask = (ss > 0.f) && (cc > 0);
        g_sscale[t] = mask ? (1.f / ss) : 0.f;
        float te = (ts == 0.f) ? 100.f : ts;
        g_tscale[t] = mask ? (-1.f / te) : 0.f;
    }
    float v = 0.f;
    #pragma unroll 8
    for (int b2 = 0; b2 < 256; b2++) v += g_vpart[b2][t];
    red[t] = v * v;
    __syncthreads();
    for (int s = 128; s; s >>= 1) { if (t < s) red[t] += red[t + s]; __syncthreads(); }
    float VV = red[0];
    __syncthreads();
    red[t] = g_qpart[t];
    __syncthreads();
    for (int s = 128; s; s >>= 1) { if (t < s) red[t] += red[t + s]; __syncthreads(); }
    if (t == 0) {
        int count = 0;
        for (int c = 0; c < Ccls; c++)
            if (ssumS[c] > 0.f && cntS[c] > 0) count++;
        float S = red[0];
        float sum_l2 = 2.f * (float)Nrows * S - 2.f * VV;
        float nf = (float)Nrows;
        float bw_raw = sum_l2 / (nf * nf - nf);
        g_expC = 1.f / (4.f * bw_raw);
        g_invcount = (count > 0) ? 1.f / (float)count : 0.f;
        out[0] = 0.f;
    }
}

// ---------------- kernel 2: fp16 mma pairwise GEMM + MMD epilogue ---------
// 128x128 tile (triangular grid), 256 threads = 8 warps (2x4), warp tile
// 64x32, m16n8k16 f16 -> f32. 4 K-chunks of 64 halves via cp.async.bulk into
// a 3-stage pipeline; ldmatrix.x4 fragments (B combines ni pairs).
#define NSTAGE  3
#define STAGEB  32768                   // A 16KB + B 16KB
#define OFF_BUF 0
#define OFF_MBAR (NSTAGE * STAGEB)
#define OFF_UP  (OFF_MBAR + 64)
#define OFF_UQ  (OFF_UP + Ccls * USTR * 4)
#define OFF_SQP (OFF_UQ + Ccls * USTR * 4)
#define OFF_SQQ (OFF_SQP + 512)
#define OFF_RED (OFF_SQQ + 512)
#define SMEM_DYN (OFF_RED + 64)

__global__ void __launch_bounds__(256, 2) k_main(
    const float* __restrict__ slab, const float* __restrict__ tlog,
    float* __restrict__ out)
{
    extern __shared__ char sm[];
    float* uPs = (float*)(sm + OFF_UP);   // [10][USTR]
    float* uQs = (float*)(sm + OFF_UQ);
    float* sqP = (float*)(sm + OFF_SQP);
    float* sqQ = (float*)(sm + OFF_SQQ);
    float* red = (float*)(sm + OFF_RED);
    uint32_t smb = smem_u32(sm);

    int tid = threadIdx.x;
    int w = tid >> 5, lane = tid & 31;
    int g = lane >> 2, t4 = lane & 3;
    int wr = w >> 2, wc = w & 3;          // warp grid 2 x 4
    int b = blockIdx.x;

    // triangular decode (bi <= bj)
    int bi = (int)((2.f * TILES + 1.f -
                    sqrtf((float)((2 * TILES + 1) * (2 * TILES + 1) - 8 * b))) * 0.5f);
    if (bi < 0) bi = 0; if (bi > TILES - 1) bi = TILES - 1;
    while (bi > 0 && bi * TILES - bi * (bi - 1) / 2 > b) bi--;
    while ((bi + 1) * TILES - (bi + 1) * bi / 2 <= b) bi++;
    int bj = bi + (b - (bi * TILES - bi * (bi - 1) / 2));

    int p0 = bi * 128, q0 = bj * 128;

    // ---- mbarrier init + prefetch first NSTAGE chunks ----
    if (tid == 0) {
        #pragma unroll
        for (int s = 0; s < NSTAGE; s++) MBAR_INIT(smb + OFF_MBAR + 8 * s, 1);
    }
    __syncthreads();
    if (tid == 0) {
        #pragma unroll
        for (int s = 0; s < NSTAGE; s++) {
            uint32_t mb = smb + OFF_MBAR + 8 * s;
            uint32_t dst = smb + OFF_BUF + s * STAGEB;
            MBAR_EXPECT_TX(mb, 2 * 16384);
            BULK_G2S(dst,          &g_xh[s][p0][0], 16384, mb);
            BULK_G2S(dst + 16384u, &g_xh[s][q0][0], 16384, mb);
        }
    }

    // ---- stage u vectors (scaled, sign-carrying) + squared norms ----
    if (tid < 128) {
        int p = p0 + tid;
        sqP[tid] = g_sq[p];
        if (p < Bsz) {
            #pragma unroll
            for (int c = 0; c < Ccls; c++)
                uPs[c * USTR + tid] = slab[(size_t)p * Ccls + c] * g_sscale[c];
        } else {
            #pragma unroll
            for (int c = 0; c < Ccls; c++)
                uPs[c * USTR + tid] = tlog[(size_t)(p - Bsz) * Ccls + c] * g_tscale[c];
        }
    } else {
        int j = tid - 128;
        int q = q0 + j;
        sqQ[j] = g_sq[q];
        if (q < Bsz) {
            #pragma unroll
            for (int c = 0; c < Ccls; c++)
                uQs[c * USTR + j] = slab[(size_t)q * Ccls + c] * g_sscale[c];
        } else {
            #pragma unroll
            for (int c = 0; c < Ccls; c++)
                uQs[c * USTR + j] = tlog[(size_t)(q - Bsz) * Ccls + c] * g_tscale[c];
        }
    }

    // per-lane ldmatrix base geometry (byte offsets inside a stage buffer)
    uint32_t rx = (uint32_t)(lane & 7);
    // A: lanes 0-7 m0(rows+0,klo) 8-15 m1(rows+8,klo) 16-23 m2(rows+0,khi) 24-31 m3(rows+8,khi)
    uint32_t baseA = (uint32_t)((wr * 64 + (lane & 7) + ((lane >> 3) & 1) * 8) * 128);
    uint32_t hiA = (uint32_t)(lane >> 4);
    // B: lanes 0-7 m0(n+0,klo) 8-15 m1(n+0,khi) 16-23 m2(n+8,klo) 24-31 m3(n+8,khi)
    uint32_t baseB = (uint32_t)(16384 + (wc * 32 + (lane & 7) + ((lane >> 4) & 1) * 8) * 128);
    uint32_t hiB = (uint32_t)((lane >> 3) & 1);

    float acc[16][4];
    #pragma unroll
    for (int i = 0; i < 16; i++)
        #pragma unroll
        for (int j = 0; j < 4; j++) acc[i][j] = 0.f;

    // ---- mainloop: 4 K-chunks of 64 halves, 3-stage pipeline ----
    #pragma unroll
    for (int ch = 0; ch < 4; ch++) {
        const int st = ch % NSTAGE;
        const int ph = ch / NSTAGE;
        MBAR_WAIT(smb + OFF_MBAR + 8 * st, ph);

        uint32_t bufb = smb + OFF_BUF + st * STAGEB;
        uint32_t fA[2][4][4];
        uint32_t fB[2][4][2];

        // load ks=0 fragments
        {
            uint32_t ka = ((hiA ^ rx) << 4);
            uint32_t kb = ((hiB ^ rx) << 4);
            #pragma unroll
            for (int mi = 0; mi < 4; mi++)
                ldsm_x4(fA[0][mi], bufb + baseA + mi * 2048u + ka);
            #pragma unroll
            for (int np = 0; np < 2; np++)
                ldsm_x4(&fB[0][2 * np][0], bufb + baseB + np * 2048u + kb);
        }
        #pragma unroll
        for (int ks = 0; ks < 4; ks++) {
            int cur = ks & 1;
            if (ks < 3) {
                uint32_t kn = (uint32_t)((ks + 1) << 1);
                uint32_t ka = (((kn | hiA) ^ rx) << 4);
                uint32_t kb = (((kn | hiB) ^ rx) << 4);
                #pragma unroll
                for (int mi = 0; mi < 4; mi++)
                    ldsm_x4(fA[cur ^ 1][mi], bufb + baseA + mi * 2048u + ka);
                #pragma unroll
                for (int np = 0; np < 2; np++)
                    ldsm_x4(&fB[cur ^ 1][2 * np][0], bufb + baseB + np * 2048u + kb);
            }
            #pragma unroll
            for (int mi = 0; mi < 4; mi++)
                #pragma unroll
                for (int ni = 0; ni < 4; ni++)
                    mma_f16(acc[mi * 4 + ni], fA[cur][mi], fB[cur][ni]);
        }
        __syncthreads();          // all warps done reading stage st
        if (ch == 0 && tid == 0) {
            uint32_t mb = smb + OFF_MBAR + 0;
            uint32_t dst = smb + OFF_BUF + 0;
            MBAR_EXPECT_TX(mb, 2 * 16384);
            BULK_G2S(dst,          &g_xh[3][p0][0], 16384, mb);
            BULK_G2S(dst + 16384u, &g_xh[3][q0][0], 16384, mb);
        }
    }

    // ---- epilogue ----
    const float Ce = g_expC;
    const float scale = g_invcount * ((bi == bj) ? 1.f : 2.f);
    float partial = 0.f;

    #pragma unroll
    for (int mi = 0; mi < 4; mi++) {
        int r0 = wr * 64 + mi * 16 + g;
        int r1 = r0 + 8;
        float up0[Ccls], up1[Ccls];
        #pragma unroll
        for (int c = 0; c < Ccls; c++) {
            up0[c] = uPs[c * USTR + r0];
            up1[c] = uPs[c * USTR + r1];
        }
        float sp0 = sqP[r0], sp1 = sqP[r1];
        #pragma unroll
        for (int ni = 0; ni < 4; ni++) {
            float* a = acc[mi * 4 + ni];
            int cbx = wc * 32 + ni * 8 + 2 * t4;
            float2 sv = *(float2*)&sqQ[cbx];
            float w00 = 0.f, w01 = 0.f, w10 = 0.f, w11 = 0.f;
            #pragma unroll
            for (int c = 0; c < Ccls; c++) {
                float2 uq = *(float2*)&uQs[c * USTR + cbx];
                w00 = fmaf(up0[c], uq.x, w00);
                w01 = fmaf(up0[c], uq.y, w01);
                w10 = fmaf(up1[c], uq.x, w10);
                w11 = fmaf(up1[c], uq.y, w11);
            }
            float l2, z, z2, z4, z8;
            l2 = fmaxf(sp0 + sv.x - 2.f * a[0], 0.f);
            z = __expf(-l2 * Ce); z2 = z * z; z4 = z2 * z2; z8 = z4 * z4;
            partial = fmaf(w00, z + z2 + z4 + z8 + z8 * z8, partial);
            l2 = fmaxf(sp0 + sv.y - 2.f * a[1], 0.f);
            z = __expf(-l2 * Ce); z2 = z * z; z4 = z2 * z2; z8 = z4 * z4;
            partial = fmaf(w01, z + z2 + z4 + z8 + z8 * z8, partial);
            l2 = fmaxf(sp1 + sv.x - 2.f * a[2], 0.f);
            z = __expf(-l2 * Ce); z2 = z * z; z4 = z2 * z2; z8 = z4 * z4;
            partial = fmaf(w10, z + z2 + z4 + z8 + z8 * z8, partial);
            l2 = fmaxf(sp1 + sv.y - 2.f * a[3], 0.f);
            z = __expf(-l2 * Ce); z2 = z * z; z4 = z2 * z2; z8 = z4 * z4;
            partial = fmaf(w11, z + z2 + z4 + z8 + z8 * z8, partial);
        }
    }
    partial *= scale;

    #pragma unroll
    for (int o = 16; o; o >>= 1) partial += __shfl_xor_sync(0xffffffffu, partial, o);
    if (lane == 0) red[w] = partial;
    __syncthreads();
    if (tid == 0) {
        float s = 0.f;
        #pragma unroll
        for (int i = 0; i < 8; i++) s += red[i];
        atomicAdd(out, s);
    }
}

// ---------------- launcher ------------------------------------------------
extern "C" void kernel_launch(void* const* d_in, const int* in_sizes, int n_in,
                              void* d_out, int out_size) {
    const float* src  = (const float*)d_in[0];
    const float* tgt  = (const float*)d_in[1];
    const float* slab = (const float*)d_in[2];
    const float* tlog = (const float*)d_in[3];
    float* out = (float*)d_out;

    static int configured = 0;
    if (!configured) {
        cudaFuncSetAttribute(k_main, cudaFuncAttributeMaxDynamicSharedMemorySize, SMEM_DYN);
        configured = 1;
    }

    k_row<<<Nrows / 32, 256>>>(src, tgt, slab, tlog, out);
    k_main<<<NBLK, 256, SMEM_DYN>>>(slab, tlog, out);
}

// round 8
// speedup vs baseline: 6.0482x; 1.4792x over previous
#include <cuda_runtime.h>
#include <cuda_fp16.h>
#include <cstdint>
#include <math.h>

#define Bsz   4096
#define Dd    256
#define Ccls  10
#define Nrows 8192
#define TILES 64          // 8192 / 128
#define NBLK  2080        // 64*65/2 triangular tiles

// ===================== device scratch ====================================
// fp16 copy, chunk-major (64 cols per chunk) and pre-swizzled:
// within a 128B row, 16B unit u of column c stored at u ^ (row&7).
__device__ __align__(16) __half g_xh[4][Nrows][64];
__device__ float g_sq[Nrows];
__device__ float g_spart[128][Ccls];
__device__ float g_tpart[128][Ccls];
__device__ int   g_cpart[128][Ccls];
__device__ float g_vpart[256][256];   // per-block column sums
__device__ float g_qpart[256];        // per-block sum of squared norms
__device__ float g_sscale[Ccls];
__device__ float g_tscale[Ccls];      // carries minus sign for target rows
__device__ float g_expC;              // 1/(4*bw_raw)
__device__ float g_invcount;
__device__ unsigned g_ctr;            // last-block counter (monotonic)

// ---------------- helpers -------------------------------------------------
__device__ __forceinline__ void mma_f16(float* d, const uint32_t* a, const uint32_t* b) {
    asm volatile(
        "mma.sync.aligned.m16n8k16.row.col.f32.f16.f16.f32 "
        "{%0,%1,%2,%3}, {%4,%5,%6,%7}, {%8,%9}, {%0,%1,%2,%3};"
        : "+f"(d[0]), "+f"(d[1]), "+f"(d[2]), "+f"(d[3])
        : "r"(a[0]), "r"(a[1]), "r"(a[2]), "r"(a[3]), "r"(b[0]), "r"(b[1]));
}
__device__ __forceinline__ void ldsm_x4(uint32_t* r, uint32_t addr) {
    asm volatile("ldmatrix.sync.aligned.m8n8.x4.shared.b16 {%0,%1,%2,%3}, [%4];"
        : "=r"(r[0]), "=r"(r[1]), "=r"(r[2]), "=r"(r[3]) : "r"(addr));
}
__device__ __forceinline__ uint32_t smem_u32(const void* p) {
    return (uint32_t)__cvta_generic_to_shared(p);
}
#define MBAR_INIT(mbar, cnt) \
    asm volatile("mbarrier.init.shared.b64 [%0], %1;" \
                 :: "r"((uint32_t)(mbar)), "r"((uint32_t)(cnt)) : "memory")
#define MBAR_EXPECT_TX(mbar, bytes) \
    asm volatile("mbarrier.arrive.expect_tx.shared.b64 _, [%0], %1;" \
                 :: "r"((uint32_t)(mbar)), "r"((uint32_t)(bytes)) : "memory")
#define BULK_G2S(dst, src, bytes, mbar) \
    asm volatile("cp.async.bulk.shared::cluster.global.mbarrier::complete_tx::bytes " \
                 "[%0], [%1], %2, [%3];" \
                 :: "r"((uint32_t)(dst)), "l"(src), "r"((uint32_t)(bytes)), \
                    "r"((uint32_t)(mbar)) : "memory")
#define MBAR_WAIT(mbar, parity) do {                                             \
    uint32_t _m = (uint32_t)(mbar); uint32_t _p = (uint32_t)(parity);            \
    uint32_t _done;                                                              \
    asm volatile("{\n\t.reg .pred p;\n\t"                                        \
        "mbarrier.try_wait.parity.acquire.cta.shared::cta.b64 p, [%1], %2;\n\t"  \
        "selp.b32 %0, 1, 0, p;\n\t}" : "=r"(_done) : "r"(_m), "r"(_p) : "memory"); \
    if (!_done) {                                                                \
        asm volatile("{\n\t.reg .pred P1;\n\t"                                   \
            "W_%=:\n\t"                                                          \
            "mbarrier.try_wait.parity.acquire.cta.shared::cta.b64 P1, [%0], %1, 0x989680;\n\t" \
            "@P1 bra.uni D_%=;\n\tbra.uni W_%=;\n\tD_%=:\n\t}"                   \
            :: "r"(_m), "r"(_p) : "memory");                                     \
    }                                                                            \
} while (0)

// ---------------- kernel 1: rows + stats + (last block) finalize ----------
__global__ void k_row(const float* __restrict__ src,
                      const float* __restrict__ tgt,
                      const float* __restrict__ slab,
                      const float* __restrict__ tlog,
                      float* __restrict__ out) {
    __shared__ float scol[8][256];
    __shared__ float bs[8];
    __shared__ int   lastFlag;
    int tid = threadIdx.x;
    int w = tid >> 5, lane = tid & 31;
    int bid = blockIdx.x;

    // ---- warp 0: label/logit column stats, shuffle-reduced ----
    if (w == 0) {
        int r = bid * 32 + lane;
        float val[Ccls];
        int bx = 0;
        if (bid < 128) {
            #pragma unroll
            for (int c = 0; c < Ccls; c++) val[c] = slab[(size_t)r * Ccls + c];
        } else {
            int rr = r - Bsz;
            float best = -1.f;
            #pragma unroll
            for (int c = 0; c < Ccls; c++) {
                val[c] = tlog[(size_t)rr * Ccls + c];
                if (val[c] > best) { best = val[c]; bx = c; }
            }
        }
        #pragma unroll
        for (int c = 0; c < Ccls; c++) {
            float x = val[c];
            #pragma unroll
            for (int o = 16; o; o >>= 1) x += __shfl_xor_sync(0xffffffffu, x, o);
            int cc = __popc(__ballot_sync(0xffffffffu, bx == c));
            if (lane == 0) {
                if (bid < 128) g_spart[bid][c] = x;
                else { g_tpart[bid - 128][c] = x; g_cpart[bid - 128][c] = cc; }
            }
        }
    }

    // ---- row norms + column sums + fp16 pre-round (pre-swizzled) ----
    #pragma unroll
    for (int i = 0; i < 8; i++) scol[w][lane + 32 * i] = 0.f;
    __syncwarp();
    float wsq = 0.f;
    int c0 = 2 * lane;                       // 0..62, even
    int uu = c0 >> 3, oo = c0 & 7;
    #pragma unroll
    for (int k = 0; k < 4; k++) {
        int row = bid * 32 + w * 4 + k;
        const float* p = (row < Bsz) ? src + (size_t)row * Dd
                                     : tgt + (size_t)(row - Bsz) * Dd;
        int rx = row & 7;
        int sw = (((uu ^ rx) << 3) | oo);    // half index within 64-half row
        float s = 0.f;
        #pragma unroll
        for (int i = 0; i < 4; i++) {
            float2 v = *(const float2*)(p + c0 + 64 * i);
            s += v.x * v.x + v.y * v.y;
            float2 acc = *(float2*)&scol[w][c0 + 64 * i];
            acc.x += v.x; acc.y += v.y;
            *(float2*)&scol[w][c0 + 64 * i] = acc;
            *(__half2*)&g_xh[i][row][sw] = __floats2half2_rn(v.x, v.y);
        }
        #pragma unroll
        for (int o = 16; o; o >>= 1) s += __shfl_xor_sync(0xffffffffu, s, o);
        if (lane == 0) { g_sq[row] = s; wsq += s; }
    }
    if (lane == 0) bs[w] = wsq;
    __syncthreads();
    float cs = 0.f;
    #pragma unroll
    for (int ww = 0; ww < 8; ww++) cs += scol[ww][tid];
    g_vpart[bid][tid] = cs;
    if (tid == 0) {
        float tot = 0.f;
        #pragma unroll
        for (int i = 0; i < 8; i++) tot += bs[i];
        g_qpart[bid] = tot;
    }

    // ---- last block finalizes ----
    __threadfence();
    if (tid == 0) {
        unsigned old = atomicAdd(&g_ctr, 1u);
        lastFlag = (((old + 1u) & 255u) == 0u);
    }
    __syncthreads();
    if (!lastFlag) return;

    __shared__ float red[256];
    __shared__ float ssumS[Ccls];
    __shared__ int   cntS[Ccls];
    int t = tid;
    if (t < Ccls) {
        float ss = 0.f, ts = 0.f; int cc = 0;
        #pragma unroll 4
        for (int b2 = 0; b2 < 128; b2++) {
            ss += g_spart[b2][t];
            ts += g_tpart[b2][t];
            cc += g_cpart[b2][t];
        }
        ssumS[t] = ss; cntS[t] = cc;
        bool mask = (ss > 0.f) && (cc > 0);
        g_sscale[t] = mask ? (1.f / ss) : 0.f;
        float te = (ts == 0.f) ? 100.f : ts;
        g_tscale[t] = mask ? (-1.f / te) : 0.f;
    }
    float v = 0.f;
    #pragma unroll 8
    for (int b2 = 0; b2 < 256; b2++) v += g_vpart[b2][t];
    red[t] = v * v;
    __syncthreads();
    for (int s = 128; s; s >>= 1) { if (t < s) red[t] += red[t + s]; __syncthreads(); }
    float VV = red[0];
    __syncthreads();
    red[t] = g_qpart[t];
    __syncthreads();
    for (int s = 128; s; s >>= 1) { if (t < s) red[t] += red[t + s]; __syncthreads(); }
    if (t == 0) {
        int count = 0;
        for (int c = 0; c < Ccls; c++)
            if (ssumS[c] > 0.f && cntS[c] > 0) count++;
        float S = red[0];
        float sum_l2 = 2.f * (float)Nrows * S - 2.f * VV;
        float nf = (float)Nrows;
        float bw_raw = sum_l2 / (nf * nf - nf);
        g_expC = 1.f / (4.f * bw_raw);
        g_invcount = (count > 0) ? 1.f / (float)count : 0.f;
        out[0] = 0.f;
    }
}

// ---------------- kernel 2: fp16 mma pairwise GEMM + MMD epilogue ---------
// 128x128 tile (triangular grid), 256 threads = 8 warps (2x4), warp tile
// 64x32, m16n8k16 f16 -> f32. 4 K-chunks of 64 halves via cp.async.bulk into
// a 3-stage pipeline; ldmatrix.x4 fragments. Weight matrix W = uP.uQ^T is
// ALSO computed on tensor cores (classes padded 10->16, u scaled x256,
// 1/65536 folded into the final scale).
#define NSTAGE  3
#define STAGEB  32768                   // A 16KB + B 16KB
#define OFF_BUF 0
#define OFF_MBAR (NSTAGE * STAGEB)
#define OFF_UPH (OFF_MBAR + 64)         // [128][24] halves, 48B stride
#define OFF_UQH (OFF_UPH + 128 * 48)
#define OFF_SQP (OFF_UQH + 128 * 48)
#define OFF_SQQ (OFF_SQP + 512)
#define OFF_RED (OFF_SQQ + 512)
#define SMEM_DYN (OFF_RED + 64)

__global__ void __launch_bounds__(256, 2) k_main(
    const float* __restrict__ slab, const float* __restrict__ tlog,
    float* __restrict__ out)
{
    extern __shared__ char sm[];
    float* sqP = (float*)(sm + OFF_SQP);
    float* sqQ = (float*)(sm + OFF_SQQ);
    float* red = (float*)(sm + OFF_RED);
    uint32_t smb = smem_u32(sm);

    int tid = threadIdx.x;
    int w = tid >> 5, lane = tid & 31;
    int g = lane >> 2, t4 = lane & 3;
    int wr = w >> 2, wc = w & 3;          // warp grid 2 x 4
    int b = blockIdx.x;

    // triangular decode (bi <= bj)
    int bi = (int)((2.f * TILES + 1.f -
                    sqrtf((float)((2 * TILES + 1) * (2 * TILES + 1) - 8 * b))) * 0.5f);
    if (bi < 0) bi = 0; if (bi > TILES - 1) bi = TILES - 1;
    while (bi > 0 && bi * TILES - bi * (bi - 1) / 2 > b) bi--;
    while ((bi + 1) * TILES - (bi + 1) * bi / 2 <= b) bi++;
    int bj = bi + (b - (bi * TILES - bi * (bi - 1) / 2));

    int p0 = bi * 128, q0 = bj * 128;

    // ---- mbarrier init + prefetch first NSTAGE chunks ----
    if (tid == 0) {
        #pragma unroll
        for (int s = 0; s < NSTAGE; s++) MBAR_INIT(smb + OFF_MBAR + 8 * s, 1);
    }
    __syncthreads();
    if (tid == 0) {
        #pragma unroll
        for (int s = 0; s < NSTAGE; s++) {
            uint32_t mb = smb + OFF_MBAR + 8 * s;
            uint32_t dst = smb + OFF_BUF + s * STAGEB;
            MBAR_EXPECT_TX(mb, 2 * 16384);
            BULK_G2S(dst,          &g_xh[s][p0][0], 16384, mb);
            BULK_G2S(dst + 16384u, &g_xh[s][q0][0], 16384, mb);
        }
    }

    // ---- stage u vectors as fp16 (x256) + squared norms ----
    {
        int half_ = tid >> 7;            // 0: P side, 1: Q side
        int j = tid & 127;
        int rr = (half_ ? q0 : p0) + j;
        uint32_t uoff = (half_ ? OFF_UQH : OFF_UPH) + (uint32_t)j * 48u;
        __half2* d = (__half2*)(sm + uoff);
        if (half_) sqQ[j] = g_sq[rr]; else sqP[j] = g_sq[rr];
        const float* base;
        const float* scl;
        if (rr < Bsz) { base = slab + (size_t)rr * Ccls; scl = g_sscale; }
        else          { base = tlog + (size_t)(rr - Bsz) * Ccls; scl = g_tscale; }
        #pragma unroll
        for (int c2 = 0; c2 < 5; c2++) {
            float a = base[2 * c2]     * scl[2 * c2]     * 256.f;
            float e = base[2 * c2 + 1] * scl[2 * c2 + 1] * 256.f;
            d[c2] = __floats2half2_rn(a, e);
        }
        #pragma unroll
        for (int c2 = 5; c2 < 12; c2++) d[c2] = __floats2half2_rn(0.f, 0.f);
    }

    // per-lane ldmatrix base geometry (byte offsets inside a stage buffer)
    uint32_t rx = (uint32_t)(lane & 7);
    uint32_t baseA = (uint32_t)((wr * 64 + (lane & 7) + ((lane >> 3) & 1) * 8) * 128);
    uint32_t hiA = (uint32_t)(lane >> 4);
    uint32_t baseB = (uint32_t)(16384 + (wc * 32 + (lane & 7) + ((lane >> 4) & 1) * 8) * 128);
    uint32_t hiB = (uint32_t)((lane >> 3) & 1);

    float acc[16][4];
    #pragma unroll
    for (int i = 0; i < 16; i++)
        #pragma unroll
        for (int j = 0; j < 4; j++) acc[i][j] = 0.f;

    // ---- mainloop: 4 K-chunks of 64 halves, 3-stage pipeline ----
    #pragma unroll
    for (int ch = 0; ch < 4; ch++) {
        const int st = ch % NSTAGE;
        const int ph = ch / NSTAGE;
        MBAR_WAIT(smb + OFF_MBAR + 8 * st, ph);

        uint32_t bufb = smb + OFF_BUF + st * STAGEB;
        uint32_t fA[2][4][4];
        uint32_t fB[2][4][2];

        {
            uint32_t ka = ((hiA ^ rx) << 4);
            uint32_t kb = ((hiB ^ rx) << 4);
            #pragma unroll
            for (int mi = 0; mi < 4; mi++)
                ldsm_x4(fA[0][mi], bufb + baseA + mi * 2048u + ka);
            #pragma unroll
            for (int np = 0; np < 2; np++)
                ldsm_x4(&fB[0][2 * np][0], bufb + baseB + np * 2048u + kb);
        }
        #pragma unroll
        for (int ks = 0; ks < 4; ks++) {
            int cur = ks & 1;
            if (ks < 3) {
                uint32_t kn = (uint32_t)((ks + 1) << 1);
                uint32_t ka = (((kn | hiA) ^ rx) << 4);
                uint32_t kb = (((kn | hiB) ^ rx) << 4);
                #pragma unroll
                for (int mi = 0; mi < 4; mi++)
                    ldsm_x4(fA[cur ^ 1][mi], bufb + baseA + mi * 2048u + ka);
                #pragma unroll
                for (int np = 0; np < 2; np++)
                    ldsm_x4(&fB[cur ^ 1][2 * np][0], bufb + baseB + np * 2048u + kb);
            }
            #pragma unroll
            for (int mi = 0; mi < 4; mi++)
                #pragma unroll
                for (int ni = 0; ni < 4; ni++)
                    mma_f16(acc[mi * 4 + ni], fA[cur][mi], fB[cur][ni]);
        }
        __syncthreads();          // all warps done reading stage st
        if (ch == 0 && tid == 0) {
            uint32_t mb = smb + OFF_MBAR + 0;
            uint32_t dst = smb + OFF_BUF + 0;
            MBAR_EXPECT_TX(mb, 2 * 16384);
            BULK_G2S(dst,          &g_xh[3][p0][0], 16384, mb);
            BULK_G2S(dst + 16384u, &g_xh[3][q0][0], 16384, mb);
        }
    }

    // ---- epilogue: W via tensor cores + gaussian kernel ----
    const float Ce = g_expC;
    const float scale = g_invcount * ((bi == bj) ? 1.f : 2.f) * (1.f / 65536.f);
    float partial = 0.f;

    // uQ fragments (once per warp): 2 x ldsm.x4 covering 32 n-rows x k16
    uint32_t fuB[2][4];
    {
        uint32_t rowuB = (uint32_t)(wc * 32 + (lane & 7) + ((lane >> 4) & 1) * 8);
        uint32_t addrB = smb + OFF_UQH + rowuB * 48u + ((uint32_t)((lane >> 3) & 1)) * 16u;
        ldsm_x4(fuB[0], addrB);
        ldsm_x4(fuB[1], addrB + 16u * 48u);
    }

    #pragma unroll
    for (int mi = 0; mi < 4; mi++) {
        int r0 = wr * 64 + mi * 16 + g;
        int r1 = r0 + 8;
        float sp0 = sqP[r0], sp1 = sqP[r1];

        // uP fragment for this mi + W tiles (4 MMAs)
        uint32_t fuA[4];
        {
            uint32_t rowuA = (uint32_t)(wr * 64 + mi * 16 + (lane & 7) + ((lane >> 3) & 1) * 8);
            ldsm_x4(fuA, smb + OFF_UPH + rowuA * 48u + ((uint32_t)(lane >> 4)) * 16u);
        }
        float wacc[4][4];
        #pragma unroll
        for (int ni = 0; ni < 4; ni++) {
            #pragma unroll
            for (int j = 0; j < 4; j++) wacc[ni][j] = 0.f;
            mma_f16(wacc[ni], fuA, &fuB[ni >> 1][(ni & 1) * 2]);
        }

        #pragma unroll
        for (int ni = 0; ni < 4; ni++) {
            float* a = acc[mi * 4 + ni];
            float* wa = wacc[ni];
            int cbx = wc * 32 + ni * 8 + 2 * t4;
            float2 sv = *(float2*)&sqQ[cbx];
            float l2, z, z2, z4, z8;
            l2 = fmaxf(sp0 + sv.x - 2.f * a[0], 0.f);
            z = __expf(-l2 * Ce); z2 = z * z; z4 = z2 * z2; z8 = z4 * z4;
            partial = fmaf(wa[0], z + z2 + z4 + z8 + z8 * z8, partial);
            l2 = fmaxf(sp0 + sv.y - 2.f * a[1], 0.f);
            z = __expf(-l2 * Ce); z2 = z * z; z4 = z2 * z2; z8 = z4 * z4;
            partial = fmaf(wa[1], z + z2 + z4 + z8 + z8 * z8, partial);
            l2 = fmaxf(sp1 + sv.x - 2.f * a[2], 0.f);
            z = __expf(-l2 * Ce); z2 = z * z; z4 = z2 * z2; z8 = z4 * z4;
            partial = fmaf(wa[2], z + z2 + z4 + z8 + z8 * z8, partial);
            l2 = fmaxf(sp1 + sv.y - 2.f * a[3], 0.f);
            z = __expf(-l2 * Ce); z2 = z * z; z4 = z2 * z2; z8 = z4 * z4;
            partial = fmaf(wa[3], z + z2 + z4 + z8 + z8 * z8, partial);
        }
    }
    partial *= scale;

    #pragma unroll
    for (int o = 16; o; o >>= 1) partial += __shfl_xor_sync(0xffffffffu, partial, o);
    if (lane == 0) red[w] = partial;
    __syncthreads();
    if (tid == 0) {
        float s = 0.f;
        #pragma unroll
        for (int i = 0; i < 8; i++) s += red[i];
        atomicAdd(out, s);
    }
}

// ---------------- launcher ------------------------------------------------
extern "C" void kernel_launch(void* const* d_in, const int* in_sizes, int n_in,
                              void* d_out, int out_size) {
    const float* src  = (const float*)d_in[0];
    const float* tgt  = (const float*)d_in[1];
    const float* slab = (const float*)d_in[2];
    const float* tlog = (const float*)d_in[3];
    float* out = (float*)d_out;

    static int configured = 0;
    if (!configured) {
        cudaFuncSetAttribute(k_main, cudaFuncAttributeMaxDynamicSharedMemorySize, SMEM_DYN);
        configured = 1;
    }

    k_row<<<Nrows / 32, 256>>>(src, tgt, slab, tlog, out);
    k_main<<<NBLK, 256, SMEM_DYN>>>(slab, tlog, out);
}